// round 14
// baseline (speedup 1.0000x reference)
#include <cuda_runtime.h>
#include <cuda_bf16.h>
#include <cstdint>
#include <cstddef>

// Problem constants
#define BB   32
#define NN   256
#define DM   512
#define NH   8
#define DH   64

typedef unsigned long long ull;
typedef __nv_bfloat16 bf16;

// Scratch (allocation-free rule: __device__ globals)
__device__ float g_pos[BB*NH*NN*NN];  // pos_scores fallback when d_out lacks room
__device__ bf16  g_ah[BB*NN*DM];      // attn output hi split (A of final gemm)
__device__ bf16  g_al[BB*NN*DM];      // attn output lo split
__device__ bf16  g_aqh[3*BB*NN*DM];   // q,k,v input hi splits (3 slabs)
__device__ bf16  g_aql[3*BB*NN*DM];   // q,k,v input lo splits
__device__ bf16  g_wh4[4*DM*DM];      // W^T hi splits: Wq,Wk,Wv,Wm slabs
__device__ bf16  g_wl4[4*DM*DM];
__device__ bf16  g_qhh[BB*NH*NN*DH], g_qhl[BB*NH*NN*DH];  // Q heads hi/lo
__device__ bf16  g_khh[BB*NH*NN*DH], g_khl[BB*NH*NN*DH];  // K heads hi/lo
__device__ bf16  g_vhh[BB*NH*NN*DH], g_vhl[BB*NH*NN*DH];  // V heads hi/lo
__device__ int   g_mask_kind;         // 0=int32, 1=float32, 2=byte

// ---- HMMA helpers (baseline PTX, not 'a'-gated) ----
__device__ __forceinline__ uint32_t smem_u32(const void* p) {
    uint32_t a;
    asm("{ .reg .u64 t; cvta.to.shared.u64 t, %1; cvt.u32.u64 %0, t; }"
        : "=r"(a) : "l"(p));
    return a;
}
__device__ __forceinline__ void mma16816(float* c, const uint32_t* a,
                                         const uint32_t* b) {
    asm volatile(
        "mma.sync.aligned.m16n8k16.row.col.f32.bf16.bf16.f32 "
        "{%0,%1,%2,%3}, {%4,%5,%6,%7}, {%8,%9}, {%0,%1,%2,%3};"
        : "+f"(c[0]), "+f"(c[1]), "+f"(c[2]), "+f"(c[3])
        : "r"(a[0]), "r"(a[1]), "r"(a[2]), "r"(a[3]), "r"(b[0]), "r"(b[1]));
}
__device__ __forceinline__ void ldmA(uint32_t* r, uint32_t addr) {
    asm volatile("ldmatrix.sync.aligned.m8n8.x4.shared.b16 {%0,%1,%2,%3}, [%4];"
        : "=r"(r[0]), "=r"(r[1]), "=r"(r[2]), "=r"(r[3]) : "r"(addr));
}
__device__ __forceinline__ void ldmB(uint32_t* r, uint32_t addr) {
    asm volatile("ldmatrix.sync.aligned.m8n8.x4.shared.b16 {%0,%1,%2,%3}, [%4];"
        : "=r"(r[0]), "=r"(r[1]), "=r"(r[2]), "=r"(r[3]) : "r"(addr));
}
// trans variant: [k][n]-stored data -> b-fragment (V tiles)
__device__ __forceinline__ void ldmVT(uint32_t* r, uint32_t addr) {
    asm volatile("ldmatrix.sync.aligned.m8n8.x4.trans.shared.b16 {%0,%1,%2,%3}, [%4];"
        : "=r"(r[0]), "=r"(r[1]), "=r"(r[2]), "=r"(r[3]) : "r"(addr));
}
// gemm smem: 64B rows, 4x16B chunks
__device__ __forceinline__ int swz(int row, int ch) {
    return row * 64 + ((ch ^ ((row >> 1) & 3)) << 4);
}
// attn smem: 128B rows (64 bf16), 8x16B chunks
__device__ __forceinline__ int swz128(int row, int ch) {
    return row * 128 + ((ch ^ (row & 7)) << 4);
}
// P smem: 512B rows (256 bf16), 32x16B chunks
__device__ __forceinline__ int swzP(int row, int ch) {
    return row * 512 + ((ch ^ (row & 7)) << 4);
}
// ---- cp.async (Ampere-baseline) ----
__device__ __forceinline__ void cpa16(uint32_t dst, const void* src) {
    asm volatile("cp.async.cg.shared.global [%0], [%1], 16;"
                 :: "r"(dst), "l"(src) : "memory");
}
__device__ __forceinline__ void cpa_commit() {
    asm volatile("cp.async.commit_group;" ::: "memory");
}
__device__ __forceinline__ void split2(float x, bf16& h, bf16& l) {
    h = __float2bfloat16(x);
    l = __float2bfloat16(x - __bfloat162float(h));
}

// ---------------------------------------------------------------------------
// Mask dtype sniffing (bool may arrive as u8/i32/f32).
// ---------------------------------------------------------------------------
__global__ void detect_mask_kind(const unsigned int* __restrict__ m) {
    __shared__ int oki, okf;
    if (threadIdx.x == 0) { oki = 1; okf = 1; }
    __syncthreads();
    for (int idx = threadIdx.x; idx < 2048; idx += 256) {
        unsigned int w = m[idx];
        if (w > 1u) oki = 0;
        if (w != 0u && w != 0x3F800000u) okf = 0;
    }
    __syncthreads();
    if (threadIdx.x == 0) g_mask_kind = oki ? 0 : (okf ? 1 : 2);
}

// ---------------------------------------------------------------------------
// Split q,k,v (3 x 4M fp32) -> bf16 hi/lo slabs. float4 per thread.
// ---------------------------------------------------------------------------
__global__ void split_qkv(const float* __restrict__ q,
                          const float* __restrict__ k,
                          const float* __restrict__ v,
                          bf16* __restrict__ hi, bf16* __restrict__ lo) {
    int gi = blockIdx.x * 256 + threadIdx.x;
    const int SLAB4 = BB * NN * DM / 4;
    int slab = gi / SLAB4;
    int r4 = gi - slab * SLAB4;
    const float* src = (slab == 0) ? q : (slab == 1) ? k : v;
    int i = r4 * 4;
    float4 x = *(const float4*)(src + i);
    bf16 h0, l0, h1, l1, h2, l2, h3, l3;
    split2(x.x, h0, l0); split2(x.y, h1, l1);
    split2(x.z, h2, l2); split2(x.w, h3, l3);
    size_t o = (size_t)slab * (BB * NN * DM) + i;
    *(__nv_bfloat162*)(hi + o)     = __nv_bfloat162(h0, h1);
    *(__nv_bfloat162*)(hi + o + 2) = __nv_bfloat162(h2, h3);
    *(__nv_bfloat162*)(lo + o)     = __nv_bfloat162(l0, l1);
    *(__nv_bfloat162*)(lo + o + 2) = __nv_bfloat162(l2, l3);
}

// ---------------------------------------------------------------------------
// Split + transpose all 4 weights [k][n] -> [n][k] hi/lo slabs. grid 4096x256.
// ---------------------------------------------------------------------------
__global__ void split_w4(const float* __restrict__ W0,
                         const float* __restrict__ W1,
                         const float* __restrict__ W2,
                         const float* __restrict__ W3,
                         bf16* __restrict__ hi, bf16* __restrict__ lo) {
    int gi = blockIdx.x * 256 + threadIdx.x;
    int w = gi >> 18, r = gi & 0x3FFFF;
    int k = r >> 9, n = r & 511;
    const float* W = (w == 0) ? W0 : (w == 1) ? W1 : (w == 2) ? W2 : W3;
    float x = W[r];
    bf16 h, l; split2(x, h, l);
    size_t o = (size_t)w * (DM * DM) + n * 512 + k;
    hi[o] = h;  lo[o] = l;
}

// ---------------------------------------------------------------------------
// HMMA GEMM body: cp.async 2-stage pipeline. CTA 128x128, 8 warps, BK=32.
// mode 0: fp32 row-major C.  mode 1: bf16 hi/lo head-split [B,H,N,DH].
// ---------------------------------------------------------------------------
__device__ __forceinline__ void issue_tile(
    uint32_t bs, int kn, int m0, int n0, int lr, int lr1, int lch,
    int so0, int so1,
    const bf16* __restrict__ Ah, const bf16* __restrict__ Al,
    const bf16* __restrict__ Bh, const bf16* __restrict__ Bl) {
    size_t ga0 = (size_t)(m0 + lr)  * 512 + kn + lch * 8;
    size_t ga1 = (size_t)(m0 + lr1) * 512 + kn + lch * 8;
    size_t gb0 = (size_t)(n0 + lr)  * 512 + kn + lch * 8;
    size_t gb1 = (size_t)(n0 + lr1) * 512 + kn + lch * 8;
    cpa16(bs +         so0, Ah + ga0);  cpa16(bs +         so1, Ah + ga1);
    cpa16(bs +  8192 + so0, Al + ga0);  cpa16(bs +  8192 + so1, Al + ga1);
    cpa16(bs + 16384 + so0, Bh + gb0);  cpa16(bs + 16384 + so1, Bh + gb1);
    cpa16(bs + 24576 + so0, Bl + gb0);  cpa16(bs + 24576 + so1, Bl + gb1);
    cpa_commit();
}

__device__ __forceinline__ void gemm_body(
    char* dsm, const bf16* __restrict__ Ah, const bf16* __restrict__ Al,
    const bf16* __restrict__ BhT, const bf16* __restrict__ BlT,
    const float* __restrict__ bias, float* __restrict__ C,
    bf16* __restrict__ Chi, bf16* __restrict__ Clo, int mode,
    int m0, int n0) {
    const uint32_t sb = smem_u32(dsm);
    const int tid = threadIdx.x, wid = tid >> 5, lane = tid & 31;
    const int wm = wid >> 2, wn = wid & 3;
    const int lr = tid >> 2, lch = tid & 3, lr1 = lr + 64;
    const int so0 = swz(lr, lch), so1 = swz(lr1, lch);

    float acc[4][4][4];
    #pragma unroll
    for (int i = 0; i < 4; i++)
        #pragma unroll
        for (int j = 0; j < 4; j++)
            #pragma unroll
            for (int t = 0; t < 4; t++) acc[i][j][t] = 0.f;

    issue_tile(sb, 0, m0, n0, lr, lr1, lch, so0, so1, Ah, Al, BhT, BlT);

    for (int c = 0; c < 16; c++) {
        if (c + 1 < 16) {
            issue_tile(sb + ((c + 1) & 1) * 32768, (c + 1) * 32,
                       m0, n0, lr, lr1, lch, so0, so1, Ah, Al, BhT, BlT);
            asm volatile("cp.async.wait_group %0;" :: "n"(1) : "memory");
        } else {
            asm volatile("cp.async.wait_group %0;" :: "n"(0) : "memory");
        }
        __syncthreads();

        const uint32_t bs = sb + (c & 1) * 32768;
        const uint32_t sbAh = bs, sbAl = bs + 8192;
        const uint32_t sbWh = bs + 16384, sbWl = bs + 24576;

        #pragma unroll
        for (int ks = 0; ks < 2; ks++) {
            const int arow = wm * 64 + (lane & 7) + ((lane >> 3) & 1) * 8;
            const int akch = ks * 2 + ((lane >> 4) & 1);
            const int nrow = wn * 32 + (lane & 7) + ((lane >> 4) & 1) * 8;
            const int nkch = ks * 2 + ((lane >> 3) & 1);

            uint32_t whf[2][4], wlf[2][4], af[4][4];
            #pragma unroll
            for (int g = 0; g < 2; g++) {
                ldmB(whf[g], sbWh + swz(nrow + g * 16, nkch));
                ldmB(wlf[g], sbWl + swz(nrow + g * 16, nkch));
            }
            #pragma unroll
            for (int mt = 0; mt < 4; mt++)
                ldmA(af[mt], sbAh + swz(arow + mt * 16, akch));
            #pragma unroll
            for (int mt = 0; mt < 4; mt++)
                #pragma unroll
                for (int nt = 0; nt < 4; nt++) {
                    mma16816(acc[mt][nt], af[mt], &whf[nt >> 1][(nt & 1) * 2]);
                    mma16816(acc[mt][nt], af[mt], &wlf[nt >> 1][(nt & 1) * 2]);
                }
            #pragma unroll
            for (int mt = 0; mt < 4; mt++)
                ldmA(af[mt], sbAl + swz(arow + mt * 16, akch));
            #pragma unroll
            for (int mt = 0; mt < 4; mt++)
                #pragma unroll
                for (int nt = 0; nt < 4; nt++)
                    mma16816(acc[mt][nt], af[mt], &whf[nt >> 1][(nt & 1) * 2]);
        }
        __syncthreads();
    }

    // ---- epilogue ----
    #pragma unroll
    for (int mt = 0; mt < 4; mt++) {
        int row = m0 + wm * 64 + mt * 16 + (lane >> 2);
        #pragma unroll
        for (int nt = 0; nt < 4; nt++) {
            int col = n0 + wn * 32 + nt * 8 + (lane & 3) * 2;
            float b0 = __ldg(&bias[col]), b1 = __ldg(&bias[col + 1]);
            float2 v0 = make_float2(acc[mt][nt][0] + b0, acc[mt][nt][1] + b1);
            float2 v1 = make_float2(acc[mt][nt][2] + b0, acc[mt][nt][3] + b1);
            if (mode == 1) {
                int h = col >> 6, d = col & 63;
                #pragma unroll
                for (int half = 0; half < 2; half++) {
                    float2 v = half ? v1 : v0;
                    int rr = row + half * 8;
                    int b = rr >> 8, n = rr & 255;
                    size_t base = (((size_t)b * NH + h) * NN + n) * DH + d;
                    bf16 h0, l0, h1, l1;
                    split2(v.x, h0, l0); split2(v.y, h1, l1);
                    *(__nv_bfloat162*)&Chi[base] = __nv_bfloat162(h0, h1);
                    *(__nv_bfloat162*)&Clo[base] = __nv_bfloat162(l0, l1);
                }
            } else {
                *(float2*)(C + (size_t)row * DM + col) = v0;
                *(float2*)(C + (size_t)(row + 8) * DM + col) = v1;
            }
        }
    }
}

// ---------------------------------------------------------------------------
// Fused launch: blocks [0,768) = Q/K/V projection tiles (tensor-bound);
// blocks [768, 768+8192) = geometric positional bias (MUFU-bound).
// ---------------------------------------------------------------------------
__global__ void __launch_bounds__(256, 2)
gemm_qkv_pos(const bf16* __restrict__ Aqh, const bf16* __restrict__ Aql,
             const bf16* __restrict__ Wh4, const bf16* __restrict__ Wl4,
             const float* __restrict__ bq, const float* __restrict__ bk,
             const float* __restrict__ bv,
             bf16* __restrict__ Qhh, bf16* __restrict__ Qhl,
             bf16* __restrict__ Khh, bf16* __restrict__ Khl,
             bf16* __restrict__ Vhh, bf16* __restrict__ Vhl,
             const float* __restrict__ box, const float* __restrict__ Wbox,
             const float* __restrict__ bbox, float* __restrict__ pos_out) {
    extern __shared__ char dsm[];
    const int bid = blockIdx.x;
    if (bid < 768) {
        int z = bid >> 8, rem = bid & 255;
        const size_t aoff = (size_t)z * (BB * NN * DM);
        const size_t woff = (size_t)z * (DM * DM);
        const float* bias = (z == 0) ? bq : (z == 1) ? bk : bv;
        bf16* Chi = (z == 0) ? Qhh : (z == 1) ? Khh : Vhh;
        bf16* Clo = (z == 0) ? Qhl : (z == 1) ? Khl : Vhl;
        gemm_body(dsm, Aqh + aoff, Aql + aoff, Wh4 + woff, Wl4 + woff,
                  bias, nullptr, Chi, Clo, 1, (rem >> 2) * 128, (rem & 3) * 128);
        return;
    }
    // ---- pos block ----
    float* scx = (float*)dsm;
    float* scy = scx + NN;
    float* slw = scy + NN;
    float* slh = slw + NN;
    float* wb  = slh + NN;     // 65 floats
    const int pid = bid - 768;
    const int i = pid & 255, b = pid >> 8;
    const int j = threadIdx.x;

    {
        const float* bj = box + ((size_t)b * NN + j) * 4;
        float x0 = bj[0], y0 = bj[1], x1 = bj[2], y1 = bj[3];
        scx[j] = 0.5f * (x0 + x1);
        scy[j] = 0.5f * (y0 + y1);
        slw[j] = __logf(x1 - x0 + 1.0f);
        slh[j] = __logf(y1 - y0 + 1.0f);
    }
    if (j < 64) wb[j] = Wbox[j];
    if (j == 0) wb[64] = bbox[0];
    __syncthreads();

    const float* bi = box + ((size_t)b * NN + i) * 4;
    float xi0 = bi[0], yi0 = bi[1], xi1 = bi[2], yi1 = bi[3];
    float cxi = 0.5f * (xi0 + xi1), cyi = 0.5f * (yi0 + yi1);
    float wi = xi1 - xi0 + 1.0f, hi = yi1 - yi0 + 1.0f;
    float invw = 1.0f / wi, invh = 1.0f / hi;
    float lwi = __logf(wi), lhi = __logf(hi);

    float p0 = __logf(fmaxf(fabsf((cxi - scx[j]) * invw), 1e-3f));
    float p1 = __logf(fmaxf(fabsf((cyi - scy[j]) * invh), 1e-3f));
    float p2 = lwi - slw[j];
    float p3 = lhi - slh[j];

    const float dmv[8] = {1.0f, 0.42169651f, 0.17782794f, 0.074989423f,
                          0.031622777f, 0.013335214f, 0.0056234132f, 0.0023713737f};
    float pc[4] = {100.f * p0, 100.f * p1, 100.f * p2, 100.f * p3};

    float s = wb[64];
    #pragma unroll
    for (int c = 0; c < 4; c++) {
        #pragma unroll
        for (int f = 0; f < 8; f++) {
            float m = pc[c] * dmv[f];
            float sn, cs;
            __sincosf(m, &sn, &cs);
            s = fmaf(sn, wb[c * 8 + f], s);
            s = fmaf(cs, wb[32 + c * 8 + f], s);
        }
    }
    float ps = fmaxf(s, 0.f);

    size_t base = (size_t)b * NH * NN * NN + (size_t)i * NN + j;
    #pragma unroll
    for (int hh = 0; hh < NH; hh++)
        pos_out[base + (size_t)hh * NN * NN] = ps;
}

// Output projection (mode 0, Wm = slab 3).
__global__ void __launch_bounds__(256, 2)
gemm_out(const bf16* __restrict__ Ah, const bf16* __restrict__ Al,
         const bf16* __restrict__ Wh4, const bf16* __restrict__ Wl4,
         const float* __restrict__ bias, float* __restrict__ C) {
    extern __shared__ char dsm[];
    gemm_body(dsm, Ah, Al, Wh4 + (size_t)3 * DM * DM, Wl4 + (size_t)3 * DM * DM,
              bias, C, nullptr, nullptr, 0, blockIdx.y * 128, blockIdx.x * 128);
}

// ---------------------------------------------------------------------------
// HMMA attention per (b, h, 64-q tile). 512 threads, 16 warps (4x4 grid).
// smem: Qh 0..8K | Ql 8..16K | KV stage0 16..48K | stage1 32K..48K |
//       S fp32 @49152 (64x264) [overlay Phi @49152, Plo @81920] |
//       mrow @116736. Total 116992.
// ---------------------------------------------------------------------------
#define AT_SQH 0
#define AT_SQL 8192
#define AT_KH(s) (16384 + (s) * 16384)
#define AT_KL(s) (24576 + (s) * 16384)
#define AT_S   49152
#define AT_PHI 49152
#define AT_PLO 81920
#define AT_MR  116736
#define AT_TOT 116992

__device__ __forceinline__ void issue_kv(char* sm8, int s,
                                         const bf16* __restrict__ Gh,
                                         const bf16* __restrict__ Gl,
                                         int kb, int tid) {
    const uint32_t sbase = smem_u32(sm8);
    int row = tid >> 3, ch = tid & 7;          // 512 threads = 64 rows x 8 chunks
    const bf16* sh = Gh + (size_t)(kb * 64 + row) * 64 + ch * 8;
    const bf16* sl = Gl + (size_t)(kb * 64 + row) * 64 + ch * 8;
    cpa16(sbase + AT_KH(s) + swz128(row, ch), sh);
    cpa16(sbase + AT_KL(s) + swz128(row, ch), sl);
    cpa_commit();
}

__global__ void __launch_bounds__(512, 1)
attn_tc(const void* __restrict__ maskp, const float* __restrict__ pos,
        bf16* __restrict__ Oh, bf16* __restrict__ Ol) {
    extern __shared__ char sm8[];
    const uint32_t sb = smem_u32(sm8);
    float* S = (float*)(sm8 + AT_S);
    unsigned char* mrow = (unsigned char*)(sm8 + AT_MR);

    const int blk = blockIdx.x;
    const int qt = blk & 3, h = (blk >> 2) & 7, b = blk >> 5;
    const int tid = threadIdx.x, wid = tid >> 5, lane = tid & 31;
    const int wm = wid >> 2, wn = wid & 3;          // 4 x 4 warp grid
    const int q0 = qt * 64;
    const int kind = g_mask_kind;

    const size_t hb = ((size_t)b * NH + h) * NN;
    const bf16* Qh = g_qhh + (hb + q0) * DH;
    const bf16* Ql = g_qhl + (hb + q0) * DH;
    const bf16* Kh = g_khh + hb * DH;
    const bf16* Kl = g_khl + hb * DH;
    const bf16* Vh = g_vhh + hb * DH;
    const bf16* Vl = g_vhl + hb * DH;

    // Prefetch K0 into stage 0
    issue_kv(sm8, 0, Kh, Kl, 0, tid);

    if (tid < 256) {
        int idx = b * NN + tid;
        bool mv;
        if (kind == 0)      mv = ((const int*)maskp)[idx] != 0;
        else if (kind == 1) mv = ((const float*)maskp)[idx] != 0.0f;
        else                mv = ((const unsigned char*)maskp)[idx] != 0;
        mrow[tid] = mv ? 1 : 0;
    }
    {
        int row = tid >> 3, ch = tid & 7;           // 64 q-rows x 8 chunks
        *(uint4*)(sm8 + AT_SQH + swz128(row, ch)) = *(const uint4*)(Qh + row * 64 + ch * 8);
        *(uint4*)(sm8 + AT_SQL + swz128(row, ch)) = *(const uint4*)(Ql + row * 64 + ch * 8);
    }
    const float* prow = pos + (size_t)b * (NH * NN * NN) + (size_t)q0 * NN;

    // ---- S = scale * Q K^T + pos, masked (HMMA) ----
    for (int kb = 0; kb < 4; kb++) {
        if (kb) __syncthreads();
        if (kb + 1 < 4) issue_kv(sm8, (kb + 1) & 1, Kh, Kl, kb + 1, tid);
        else            issue_kv(sm8, 0, Vh, Vl, 0, tid);   // V0 prefetch
        asm volatile("cp.async.wait_group %0;" :: "n"(1) : "memory");
        __syncthreads();

        const int st = kb & 1;
        float acc[2][4] = {{0.f,0.f,0.f,0.f},{0.f,0.f,0.f,0.f}};
        #pragma unroll
        for (int ks = 0; ks < 4; ks++) {
            const int arow = wm * 16 + (lane & 7) + ((lane >> 3) & 1) * 8;
            const int akch = ks * 2 + ((lane >> 4) & 1);
            const int nrow = wn * 16 + (lane & 7) + ((lane >> 4) & 1) * 8;
            const int nkch = ks * 2 + ((lane >> 3) & 1);
            uint32_t aH[4], aL[4], bH[4], bL[4];
            ldmA(aH, sb + AT_SQH + swz128(arow, akch));
            ldmA(aL, sb + AT_SQL + swz128(arow, akch));
            ldmB(bH, sb + AT_KH(st) + swz128(nrow, nkch));
            ldmB(bL, sb + AT_KL(st) + swz128(nrow, nkch));
            #pragma unroll
            for (int nt = 0; nt < 2; nt++) {
                mma16816(acc[nt], aH, bH + nt * 2);
                mma16816(acc[nt], aH, bL + nt * 2);
                mma16816(acc[nt], aL, bH + nt * 2);
            }
        }
        #pragma unroll
        for (int nt = 0; nt < 2; nt++) {
            int col = kb * 64 + wn * 16 + nt * 8 + (lane & 3) * 2;
            #pragma unroll
            for (int half = 0; half < 2; half++) {
                int r = wm * 16 + (lane >> 2) + half * 8;
                float a0 = acc[nt][half * 2 + 0], a1 = acc[nt][half * 2 + 1];
                float v0 = mrow[col]     ? -1e9f : fmaf(a0, 0.125f, prow[r * NN + col]);
                float v1 = mrow[col + 1] ? -1e9f : fmaf(a1, 0.125f, prow[r * NN + col + 1]);
                S[r * 264 + col]     = v0;
                S[r * 264 + col + 1] = v1;
            }
        }
    }
    __syncthreads();

    // ---- softmax: 8 lanes per row (512 threads -> 64 rows) ----
    {
        int row = tid >> 3, sub = tid & 7;
        float* Sr = S + row * 264;
        float mx = -3.4e38f;
        #pragma unroll
        for (int t = 0; t < 32; t++) mx = fmaxf(mx, Sr[sub + t * 8]);
        #pragma unroll
        for (int o = 4; o > 0; o >>= 1)
            mx = fmaxf(mx, __shfl_xor_sync(0xffffffffu, mx, o));
        float ssum = 0.f;
        #pragma unroll
        for (int t = 0; t < 32; t++) {
            float e = __expf(Sr[sub + t * 8] - mx);
            Sr[sub + t * 8] = e;
            ssum += e;
        }
        #pragma unroll
        for (int o = 4; o > 0; o >>= 1)
            ssum += __shfl_xor_sync(0xffffffffu, ssum, o);
        float inv = 1.0f / ssum;
        #pragma unroll
        for (int t = 0; t < 32; t++) Sr[sub + t * 8] *= inv;
    }
    __syncthreads();

    // ---- convert P (fp32 S) -> bf16 hi/lo, overlaid on S region ----
    {
        int row = tid >> 3, cb = (tid & 7) * 4;
        float tmp[32];
        #pragma unroll
        for (int c4 = 0; c4 < 4; c4++)
            #pragma unroll
            for (int e = 0; e < 8; e++)
                tmp[c4 * 8 + e] = S[row * 264 + (cb + c4) * 8 + e];
        __syncthreads();
        #pragma unroll
        for (int c4 = 0; c4 < 4; c4++) {
            uint32_t hi4[4], lo4[4];
            #pragma unroll
            for (int p = 0; p < 4; p++) {
                float x0 = tmp[c4 * 8 + p * 2], x1 = tmp[c4 * 8 + p * 2 + 1];
                bf16 h0, l0, h1, l1;
                split2(x0, h0, l0); split2(x1, h1, l1);
                __nv_bfloat162 hp(h0, h1), lp(l0, l1);
                hi4[p] = *(uint32_t*)&hp;
                lo4[p] = *(uint32_t*)&lp;
            }
            *(uint4*)(sm8 + AT_PHI + swzP(row, cb + c4)) = make_uint4(hi4[0], hi4[1], hi4[2], hi4[3]);
            *(uint4*)(sm8 + AT_PLO + swzP(row, cb + c4)) = make_uint4(lo4[0], lo4[1], lo4[2], lo4[3]);
        }
    }

    // ---- O = P V (HMMA, V via ldmatrix.trans, double-buffered stages) ----
    float oacc[2][4] = {{0.f,0.f,0.f,0.f},{0.f,0.f,0.f,0.f}};
    for (int kb = 0; kb < 4; kb++) {
        __syncthreads();
        if (kb + 1 < 4) {
            issue_kv(sm8, (kb + 1) & 1, Vh, Vl, kb + 1, tid);
            asm volatile("cp.async.wait_group %0;" :: "n"(1) : "memory");
        } else {
            asm volatile("cp.async.wait_group %0;" :: "n"(0) : "memory");
        }
        __syncthreads();
        const int st = kb & 1;
        #pragma unroll
        for (int ks = 0; ks < 4; ks++) {
            const int arow = wm * 16 + (lane & 7) + ((lane >> 3) & 1) * 8;
            const int akch = kb * 8 + ks * 2 + ((lane >> 4) & 1);
            const int vrow = ks * 16 + (lane & 7) + ((lane >> 3) & 1) * 8;
            const int vch  = wn * 2 + ((lane >> 4) & 1);
            uint32_t pH[4], pL[4], vH[4], vL[4];
            ldmA(pH, sb + AT_PHI + swzP(arow, akch));
            ldmA(pL, sb + AT_PLO + swzP(arow, akch));
            ldmVT(vH, sb + AT_KH(st) + swz128(vrow, vch));
            ldmVT(vL, sb + AT_KL(st) + swz128(vrow, vch));
            #pragma unroll
            for (int nt = 0; nt < 2; nt++) {
                mma16816(oacc[nt], pH, vH + nt * 2);
                mma16816(oacc[nt], pH, vL + nt * 2);
                mma16816(oacc[nt], pL, vH + nt * 2);
            }
        }
    }

    // ---- store O directly as bf16 hi/lo (A of output projection) ----
    #pragma unroll
    for (int nt = 0; nt < 2; nt++) {
        int dcol = h * 64 + wn * 16 + nt * 8 + (lane & 3) * 2;
        #pragma unroll
        for (int half = 0; half < 2; half++) {
            int drow = q0 + wm * 16 + (lane >> 2) + half * 8;
            float x0 = oacc[nt][half * 2], x1 = oacc[nt][half * 2 + 1];
            bf16 h0, l0, h1, l1;
            split2(x0, h0, l0); split2(x1, h1, l1);
            size_t base = ((size_t)b * NN + drow) * DM + dcol;
            *(__nv_bfloat162*)&Oh[base] = __nv_bfloat162(h0, h1);
            *(__nv_bfloat162*)&Ol[base] = __nv_bfloat162(l0, l1);
        }
    }
}

// ---------------------------------------------------------------------------
extern "C" void kernel_launch(void* const* d_in, const int* in_sizes, int n_in,
                              void* d_out, int out_size) {
    const float *v, *k, *q, *box, *Wq, *bq, *Wk, *bk, *Wv, *bv, *Wm, *bm, *Wbox, *bbox;
    const void* mask;

    if (in_sizes[0] == BB * NN * DM) {
        v    = (const float*)d_in[0];
        k    = (const float*)d_in[1];
        q    = (const float*)d_in[2];
        box  = (const float*)d_in[3];
        mask = d_in[4];
        int wb = 5;
        for (int i = 5; i < n_in; i++) {
            if (in_sizes[i] == DM * DM) { wb = i; break; }
        }
        Wq   = (const float*)d_in[wb + 0];
        bq   = (const float*)d_in[wb + 1];
        Wk   = (const float*)d_in[wb + 2];
        bk   = (const float*)d_in[wb + 3];
        Wv   = (const float*)d_in[wb + 4];
        bv   = (const float*)d_in[wb + 5];
        Wm   = (const float*)d_in[wb + 6];
        bm   = (const float*)d_in[wb + 7];
        Wbox = (const float*)d_in[wb + 8];
        bbox = (const float*)d_in[wb + 9];
    } else {
        Wbox = (const float*)d_in[0];
        Wk   = (const float*)d_in[1];
        Wm   = (const float*)d_in[2];
        Wq   = (const float*)d_in[3];
        Wv   = (const float*)d_in[4];
        bbox = (const float*)d_in[5];
        bk   = (const float*)d_in[6];
        bm   = (const float*)d_in[7];
        bq   = (const float*)d_in[8];
        bv   = (const float*)d_in[9];
        box  = (const float*)d_in[10];
        int idx = 11;
        if (idx < n_in && in_sizes[idx] == 1) idx++;
        k    = (const float*)d_in[idx + 0];
        mask = d_in[idx + 1];
        q    = (const float*)d_in[idx + 2];
        v    = (const float*)d_in[idx + 3];
    }

    const size_t ATTED_ELEMS = (size_t)BB * NN * DM;
    const size_t POS_ELEMS   = (size_t)BB * NH * NN * NN;
    float* out = (float*)d_out;

    float *posA;
    bf16 *ahA, *alA, *aqhA, *aqlA, *wh4A, *wl4A;
    bf16 *qhhA, *qhlA, *khhA, *khlA, *vhhA, *vhlA;
    cudaGetSymbolAddress((void**)&posA, g_pos);
    cudaGetSymbolAddress((void**)&ahA,  g_ah);
    cudaGetSymbolAddress((void**)&alA,  g_al);
    cudaGetSymbolAddress((void**)&aqhA, g_aqh);
    cudaGetSymbolAddress((void**)&aqlA, g_aql);
    cudaGetSymbolAddress((void**)&wh4A, g_wh4);
    cudaGetSymbolAddress((void**)&wl4A, g_wl4);
    cudaGetSymbolAddress((void**)&qhhA, g_qhh);
    cudaGetSymbolAddress((void**)&qhlA, g_qhl);
    cudaGetSymbolAddress((void**)&khhA, g_khh);
    cudaGetSymbolAddress((void**)&khlA, g_khl);
    cudaGetSymbolAddress((void**)&vhhA, g_vhh);
    cudaGetSymbolAddress((void**)&vhlA, g_vhl);

    float* atted;
    float* pos_out;
    if ((size_t)out_size >= ATTED_ELEMS + POS_ELEMS) {
        atted   = out;
        pos_out = out + ATTED_ELEMS;
    } else if ((size_t)out_size == POS_ELEMS) {
        pos_out = out;
        atted   = posA;            // scratch sink (unused result)
    } else {
        atted   = out;
        pos_out = posA;
    }

    detect_mask_kind<<<1, 256>>>((const unsigned int*)mask);

    cudaFuncSetAttribute(gemm_qkv_pos,
                         cudaFuncAttributeMaxDynamicSharedMemorySize, 65536);
    cudaFuncSetAttribute(gemm_out,
                         cudaFuncAttributeMaxDynamicSharedMemorySize, 65536);
    cudaFuncSetAttribute(attn_tc,
                         cudaFuncAttributeMaxDynamicSharedMemorySize, AT_TOT);

    // Upfront splits: all 4 weights, then q/k/v inputs
    split_w4<<<4096, 256>>>(Wq, Wk, Wv, Wm, wh4A, wl4A);
    split_qkv<<<3 * (BB * NN * DM) / (4 * 256), 256>>>(q, k, v, aqhA, aqlA);

    // Fused: 768 GEMM tile blocks + 8192 pos blocks in one launch
    gemm_qkv_pos<<<768 + BB * NN, 256, 65536>>>(
        aqhA, aqlA, wh4A, wl4A, bq, bk, bv,
        qhhA, qhlA, khhA, khlA, vhhA, vhlA,
        box, Wbox, bbox, pos_out);

    // Attention: 64-q tiles, 512 threads
    attn_tc<<<BB * NH * 4, 512, AT_TOT>>>(mask, pos_out, ahA, alA);

    // Output projection
    gemm_out<<<dim3(4, 64), 256, 65536>>>(ahA, alA, wh4A, wl4A, bm, atted);
}

// round 16
// speedup vs baseline: 1.0387x; 1.0387x over previous
#include <cuda_runtime.h>
#include <cuda_bf16.h>
#include <cstdint>
#include <cstddef>

// Problem constants
#define BB   32
#define NN   256
#define DM   512
#define NH   8
#define DH   64

typedef unsigned long long ull;
typedef __nv_bfloat16 bf16;

// Scratch (allocation-free rule: __device__ globals)
__device__ float g_pos[BB*NH*NN*NN];  // pos_scores fallback when d_out lacks room
__device__ bf16  g_ah[BB*NN*DM];      // attn output hi split (A of final gemm)
__device__ bf16  g_al[BB*NN*DM];      // attn output lo split
__device__ bf16  g_aqh[3*BB*NN*DM];   // q,k,v input hi splits (3 slabs)
__device__ bf16  g_aql[3*BB*NN*DM];   // q,k,v input lo splits
__device__ bf16  g_wh4[4*DM*DM];      // W^T hi splits: Wq,Wk,Wv,Wm slabs
__device__ bf16  g_wl4[4*DM*DM];
__device__ bf16  g_qhh[BB*NH*NN*DH], g_qhl[BB*NH*NN*DH];  // Q heads hi/lo
__device__ bf16  g_khh[BB*NH*NN*DH], g_khl[BB*NH*NN*DH];  // K heads hi/lo
__device__ bf16  g_vhh[BB*NH*NN*DH], g_vhl[BB*NH*NN*DH];  // V heads hi/lo
__device__ int   g_mask_kind;         // 0=int32, 1=float32, 2=byte

// ---- HMMA helpers (baseline PTX, not 'a'-gated) ----
__device__ __forceinline__ uint32_t smem_u32(const void* p) {
    uint32_t a;
    asm("{ .reg .u64 t; cvta.to.shared.u64 t, %1; cvt.u32.u64 %0, t; }"
        : "=r"(a) : "l"(p));
    return a;
}
__device__ __forceinline__ void mma16816(float* c, const uint32_t* a,
                                         const uint32_t* b) {
    asm volatile(
        "mma.sync.aligned.m16n8k16.row.col.f32.bf16.bf16.f32 "
        "{%0,%1,%2,%3}, {%4,%5,%6,%7}, {%8,%9}, {%0,%1,%2,%3};"
        : "+f"(c[0]), "+f"(c[1]), "+f"(c[2]), "+f"(c[3])
        : "r"(a[0]), "r"(a[1]), "r"(a[2]), "r"(a[3]), "r"(b[0]), "r"(b[1]));
}
__device__ __forceinline__ void ldmA(uint32_t* r, uint32_t addr) {
    asm volatile("ldmatrix.sync.aligned.m8n8.x4.shared.b16 {%0,%1,%2,%3}, [%4];"
        : "=r"(r[0]), "=r"(r[1]), "=r"(r[2]), "=r"(r[3]) : "r"(addr));
}
__device__ __forceinline__ void ldmB(uint32_t* r, uint32_t addr) {
    asm volatile("ldmatrix.sync.aligned.m8n8.x4.shared.b16 {%0,%1,%2,%3}, [%4];"
        : "=r"(r[0]), "=r"(r[1]), "=r"(r[2]), "=r"(r[3]) : "r"(addr));
}
// trans variant: [k][n]-stored data -> b-fragment (V tiles)
__device__ __forceinline__ void ldmVT(uint32_t* r, uint32_t addr) {
    asm volatile("ldmatrix.sync.aligned.m8n8.x4.trans.shared.b16 {%0,%1,%2,%3}, [%4];"
        : "=r"(r[0]), "=r"(r[1]), "=r"(r[2]), "=r"(r[3]) : "r"(addr));
}
// gemm smem: 64B rows, 4x16B chunks
__device__ __forceinline__ int swz(int row, int ch) {
    return row * 64 + ((ch ^ ((row >> 1) & 3)) << 4);
}
// attn smem: 128B rows (64 bf16), 8x16B chunks
__device__ __forceinline__ int swz128(int row, int ch) {
    return row * 128 + ((ch ^ (row & 7)) << 4);
}
// P smem: 512B rows (256 bf16), 32x16B chunks
__device__ __forceinline__ int swzP(int row, int ch) {
    return row * 512 + ((ch ^ (row & 7)) << 4);
}
// ---- cp.async (Ampere-baseline) ----
__device__ __forceinline__ void cpa16(uint32_t dst, const void* src) {
    asm volatile("cp.async.cg.shared.global [%0], [%1], 16;"
                 :: "r"(dst), "l"(src) : "memory");
}
__device__ __forceinline__ void cpa_commit() {
    asm volatile("cp.async.commit_group;" ::: "memory");
}
__device__ __forceinline__ void split2(float x, bf16& h, bf16& l) {
    h = __float2bfloat16(x);
    l = __float2bfloat16(x - __bfloat162float(h));
}

// ---------------------------------------------------------------------------
// Mask dtype sniffing (bool may arrive as u8/i32/f32).
// ---------------------------------------------------------------------------
__global__ void detect_mask_kind(const unsigned int* __restrict__ m) {
    __shared__ int oki, okf;
    if (threadIdx.x == 0) { oki = 1; okf = 1; }
    __syncthreads();
    for (int idx = threadIdx.x; idx < 2048; idx += 256) {
        unsigned int w = m[idx];
        if (w > 1u) oki = 0;
        if (w != 0u && w != 0x3F800000u) okf = 0;
    }
    __syncthreads();
    if (threadIdx.x == 0) g_mask_kind = oki ? 0 : (okf ? 1 : 2);
}

// ---------------------------------------------------------------------------
// Merged split kernel: blocks [0,12288) split q/k/v (float4 each);
// blocks [12288, 16384) split+transpose the 4 weights.
// ---------------------------------------------------------------------------
__global__ void split_all(const float* __restrict__ q,
                          const float* __restrict__ k,
                          const float* __restrict__ v,
                          const float* __restrict__ W0,
                          const float* __restrict__ W1,
                          const float* __restrict__ W2,
                          const float* __restrict__ W3,
                          bf16* __restrict__ ahi, bf16* __restrict__ alo,
                          bf16* __restrict__ whi, bf16* __restrict__ wlo) {
    const int bid = blockIdx.x;
    if (bid < 12288) {
        int gi = bid * 256 + threadIdx.x;
        const int SLAB4 = BB * NN * DM / 4;
        int slab = gi / SLAB4;
        int r4 = gi - slab * SLAB4;
        const float* src = (slab == 0) ? q : (slab == 1) ? k : v;
        int i = r4 * 4;
        float4 x = *(const float4*)(src + i);
        bf16 h0, l0, h1, l1, h2, l2, h3, l3;
        split2(x.x, h0, l0); split2(x.y, h1, l1);
        split2(x.z, h2, l2); split2(x.w, h3, l3);
        size_t o = (size_t)slab * (BB * NN * DM) + i;
        *(__nv_bfloat162*)(ahi + o)     = __nv_bfloat162(h0, h1);
        *(__nv_bfloat162*)(ahi + o + 2) = __nv_bfloat162(h2, h3);
        *(__nv_bfloat162*)(alo + o)     = __nv_bfloat162(l0, l1);
        *(__nv_bfloat162*)(alo + o + 2) = __nv_bfloat162(l2, l3);
    } else {
        int gi = (bid - 12288) * 256 + threadIdx.x;
        int w = gi >> 18, r = gi & 0x3FFFF;
        int kk = r >> 9, n = r & 511;
        const float* W = (w == 0) ? W0 : (w == 1) ? W1 : (w == 2) ? W2 : W3;
        float x = W[r];
        bf16 h, l; split2(x, h, l);
        size_t o = (size_t)w * (DM * DM) + n * 512 + kk;
        whi[o] = h;  wlo[o] = l;
    }
}

// ---------------------------------------------------------------------------
// HMMA GEMM body: cp.async 2-stage pipeline. CTA 128x128, 8 warps, BK=32.
// mode 0: fp32 row-major C.  mode 1: bf16 hi/lo head-split [B,H,N,DH].
// ---------------------------------------------------------------------------
__device__ __forceinline__ void issue_tile(
    uint32_t bs, int kn, int m0, int n0, int lr, int lr1, int lch,
    int so0, int so1,
    const bf16* __restrict__ Ah, const bf16* __restrict__ Al,
    const bf16* __restrict__ Bh, const bf16* __restrict__ Bl) {
    size_t ga0 = (size_t)(m0 + lr)  * 512 + kn + lch * 8;
    size_t ga1 = (size_t)(m0 + lr1) * 512 + kn + lch * 8;
    size_t gb0 = (size_t)(n0 + lr)  * 512 + kn + lch * 8;
    size_t gb1 = (size_t)(n0 + lr1) * 512 + kn + lch * 8;
    cpa16(bs +         so0, Ah + ga0);  cpa16(bs +         so1, Ah + ga1);
    cpa16(bs +  8192 + so0, Al + ga0);  cpa16(bs +  8192 + so1, Al + ga1);
    cpa16(bs + 16384 + so0, Bh + gb0);  cpa16(bs + 16384 + so1, Bh + gb1);
    cpa16(bs + 24576 + so0, Bl + gb0);  cpa16(bs + 24576 + so1, Bl + gb1);
    cpa_commit();
}

__device__ __forceinline__ void gemm_body(
    char* dsm, const bf16* __restrict__ Ah, const bf16* __restrict__ Al,
    const bf16* __restrict__ BhT, const bf16* __restrict__ BlT,
    const float* __restrict__ bias, float* __restrict__ C,
    bf16* __restrict__ Chi, bf16* __restrict__ Clo, int mode,
    int m0, int n0) {
    const uint32_t sb = smem_u32(dsm);
    const int tid = threadIdx.x, wid = tid >> 5, lane = tid & 31;
    const int wm = wid >> 2, wn = wid & 3;
    const int lr = tid >> 2, lch = tid & 3, lr1 = lr + 64;
    const int so0 = swz(lr, lch), so1 = swz(lr1, lch);

    float acc[4][4][4];
    #pragma unroll
    for (int i = 0; i < 4; i++)
        #pragma unroll
        for (int j = 0; j < 4; j++)
            #pragma unroll
            for (int t = 0; t < 4; t++) acc[i][j][t] = 0.f;

    issue_tile(sb, 0, m0, n0, lr, lr1, lch, so0, so1, Ah, Al, BhT, BlT);

    for (int c = 0; c < 16; c++) {
        if (c + 1 < 16) {
            issue_tile(sb + ((c + 1) & 1) * 32768, (c + 1) * 32,
                       m0, n0, lr, lr1, lch, so0, so1, Ah, Al, BhT, BlT);
            asm volatile("cp.async.wait_group %0;" :: "n"(1) : "memory");
        } else {
            asm volatile("cp.async.wait_group %0;" :: "n"(0) : "memory");
        }
        __syncthreads();

        const uint32_t bs = sb + (c & 1) * 32768;
        const uint32_t sbAh = bs, sbAl = bs + 8192;
        const uint32_t sbWh = bs + 16384, sbWl = bs + 24576;

        #pragma unroll
        for (int ks = 0; ks < 2; ks++) {
            const int arow = wm * 64 + (lane & 7) + ((lane >> 3) & 1) * 8;
            const int akch = ks * 2 + ((lane >> 4) & 1);
            const int nrow = wn * 32 + (lane & 7) + ((lane >> 4) & 1) * 8;
            const int nkch = ks * 2 + ((lane >> 3) & 1);

            uint32_t whf[2][4], wlf[2][4], af[4][4];
            #pragma unroll
            for (int g = 0; g < 2; g++) {
                ldmB(whf[g], sbWh + swz(nrow + g * 16, nkch));
                ldmB(wlf[g], sbWl + swz(nrow + g * 16, nkch));
            }
            #pragma unroll
            for (int mt = 0; mt < 4; mt++)
                ldmA(af[mt], sbAh + swz(arow + mt * 16, akch));
            #pragma unroll
            for (int mt = 0; mt < 4; mt++)
                #pragma unroll
                for (int nt = 0; nt < 4; nt++) {
                    mma16816(acc[mt][nt], af[mt], &whf[nt >> 1][(nt & 1) * 2]);
                    mma16816(acc[mt][nt], af[mt], &wlf[nt >> 1][(nt & 1) * 2]);
                }
            #pragma unroll
            for (int mt = 0; mt < 4; mt++)
                ldmA(af[mt], sbAl + swz(arow + mt * 16, akch));
            #pragma unroll
            for (int mt = 0; mt < 4; mt++)
                #pragma unroll
                for (int nt = 0; nt < 4; nt++)
                    mma16816(acc[mt][nt], af[mt], &whf[nt >> 1][(nt & 1) * 2]);
        }
        __syncthreads();
    }

    // ---- epilogue ----
    #pragma unroll
    for (int mt = 0; mt < 4; mt++) {
        int row = m0 + wm * 64 + mt * 16 + (lane >> 2);
        #pragma unroll
        for (int nt = 0; nt < 4; nt++) {
            int col = n0 + wn * 32 + nt * 8 + (lane & 3) * 2;
            float b0 = __ldg(&bias[col]), b1 = __ldg(&bias[col + 1]);
            float2 v0 = make_float2(acc[mt][nt][0] + b0, acc[mt][nt][1] + b1);
            float2 v1 = make_float2(acc[mt][nt][2] + b0, acc[mt][nt][3] + b1);
            if (mode == 1) {
                int h = col >> 6, d = col & 63;
                #pragma unroll
                for (int half = 0; half < 2; half++) {
                    float2 v = half ? v1 : v0;
                    int rr = row + half * 8;
                    int b = rr >> 8, n = rr & 255;
                    size_t base = (((size_t)b * NH + h) * NN + n) * DH + d;
                    bf16 h0, l0, h1, l1;
                    split2(v.x, h0, l0); split2(v.y, h1, l1);
                    *(__nv_bfloat162*)&Chi[base] = __nv_bfloat162(h0, h1);
                    *(__nv_bfloat162*)&Clo[base] = __nv_bfloat162(l0, l1);
                }
            } else {
                *(float2*)(C + (size_t)row * DM + col) = v0;
                *(float2*)(C + (size_t)(row + 8) * DM + col) = v1;
            }
        }
    }
}

// ---------------------------------------------------------------------------
// Fused launch: blocks [0,768) = Q/K/V projection tiles (tensor-bound);
// blocks [768, 768+8192) = geometric positional bias (MUFU-bound).
// ---------------------------------------------------------------------------
__global__ void __launch_bounds__(256, 2)
gemm_qkv_pos(const bf16* __restrict__ Aqh, const bf16* __restrict__ Aql,
             const bf16* __restrict__ Wh4, const bf16* __restrict__ Wl4,
             const float* __restrict__ bq, const float* __restrict__ bk,
             const float* __restrict__ bv,
             bf16* __restrict__ Qhh, bf16* __restrict__ Qhl,
             bf16* __restrict__ Khh, bf16* __restrict__ Khl,
             bf16* __restrict__ Vhh, bf16* __restrict__ Vhl,
             const float* __restrict__ box, const float* __restrict__ Wbox,
             const float* __restrict__ bbox, float* __restrict__ pos_out) {
    extern __shared__ char dsm[];
    const int bid = blockIdx.x;
    if (bid < 768) {
        int z = bid >> 8, rem = bid & 255;
        const size_t aoff = (size_t)z * (BB * NN * DM);
        const size_t woff = (size_t)z * (DM * DM);
        const float* bias = (z == 0) ? bq : (z == 1) ? bk : bv;
        bf16* Chi = (z == 0) ? Qhh : (z == 1) ? Khh : Vhh;
        bf16* Clo = (z == 0) ? Qhl : (z == 1) ? Khl : Vhl;
        gemm_body(dsm, Aqh + aoff, Aql + aoff, Wh4 + woff, Wl4 + woff,
                  bias, nullptr, Chi, Clo, 1, (rem >> 2) * 128, (rem & 3) * 128);
        return;
    }
    // ---- pos block ----
    float* scx = (float*)dsm;
    float* scy = scx + NN;
    float* slw = scy + NN;
    float* slh = slw + NN;
    float* wb  = slh + NN;     // 65 floats
    const int pid = bid - 768;
    const int i = pid & 255, b = pid >> 8;
    const int j = threadIdx.x;

    {
        const float* bj = box + ((size_t)b * NN + j) * 4;
        float x0 = bj[0], y0 = bj[1], x1 = bj[2], y1 = bj[3];
        scx[j] = 0.5f * (x0 + x1);
        scy[j] = 0.5f * (y0 + y1);
        slw[j] = __logf(x1 - x0 + 1.0f);
        slh[j] = __logf(y1 - y0 + 1.0f);
    }
    if (j < 64) wb[j] = Wbox[j];
    if (j == 0) wb[64] = bbox[0];
    __syncthreads();

    const float* bi = box + ((size_t)b * NN + i) * 4;
    float xi0 = bi[0], yi0 = bi[1], xi1 = bi[2], yi1 = bi[3];
    float cxi = 0.5f * (xi0 + xi1), cyi = 0.5f * (yi0 + yi1);
    float wi = xi1 - xi0 + 1.0f, hi = yi1 - yi0 + 1.0f;
    float invw = 1.0f / wi, invh = 1.0f / hi;
    float lwi = __logf(wi), lhi = __logf(hi);

    float p0 = __logf(fmaxf(fabsf((cxi - scx[j]) * invw), 1e-3f));
    float p1 = __logf(fmaxf(fabsf((cyi - scy[j]) * invh), 1e-3f));
    float p2 = lwi - slw[j];
    float p3 = lhi - slh[j];

    const float dmv[8] = {1.0f, 0.42169651f, 0.17782794f, 0.074989423f,
                          0.031622777f, 0.013335214f, 0.0056234132f, 0.0023713737f};
    float pc[4] = {100.f * p0, 100.f * p1, 100.f * p2, 100.f * p3};

    float s = wb[64];
    #pragma unroll
    for (int c = 0; c < 4; c++) {
        #pragma unroll
        for (int f = 0; f < 8; f++) {
            float m = pc[c] * dmv[f];
            float sn, cs;
            __sincosf(m, &sn, &cs);
            s = fmaf(sn, wb[c * 8 + f], s);
            s = fmaf(cs, wb[32 + c * 8 + f], s);
        }
    }
    float ps = fmaxf(s, 0.f);

    size_t base = (size_t)b * NH * NN * NN + (size_t)i * NN + j;
    #pragma unroll
    for (int hh = 0; hh < NH; hh++)
        pos_out[base + (size_t)hh * NN * NN] = ps;
}

// Output projection (mode 0, Wm = slab 3).
__global__ void __launch_bounds__(256, 2)
gemm_out(const bf16* __restrict__ Ah, const bf16* __restrict__ Al,
         const bf16* __restrict__ Wh4, const bf16* __restrict__ Wl4,
         const float* __restrict__ bias, float* __restrict__ C) {
    extern __shared__ char dsm[];
    gemm_body(dsm, Ah, Al, Wh4 + (size_t)3 * DM * DM, Wl4 + (size_t)3 * DM * DM,
              bias, C, nullptr, nullptr, 0, blockIdx.y * 128, blockIdx.x * 128);
}

// ---------------------------------------------------------------------------
// HMMA attention per (b, h, 32-q tile). cp.async double-buffered K/V stages.
// (R13 configuration: 256 threads, 2 CTAs/SM — best measured.)
// ---------------------------------------------------------------------------
#define AT_SQH 0
#define AT_SQL 4096
#define AT_KH(s) (8192 + (s) * 16384)
#define AT_KL(s) (16384 + (s) * 16384)
#define AT_S   40960
#define AT_PHI 40960
#define AT_PLO 57344
#define AT_MR  74752
#define AT_TOT 75008

__device__ __forceinline__ void issue_kv(char* sm8, int s,
                                         const bf16* __restrict__ Gh,
                                         const bf16* __restrict__ Gl,
                                         int kb, int tid) {
    const uint32_t sbase = smem_u32(sm8);
    #pragma unroll
    for (int t = 0; t < 2; t++) {
        int idx = t * 256 + tid;
        int row = idx >> 3, ch = idx & 7;
        const bf16* sh = Gh + (size_t)(kb * 64 + row) * 64 + ch * 8;
        const bf16* sl = Gl + (size_t)(kb * 64 + row) * 64 + ch * 8;
        cpa16(sbase + AT_KH(s) + swz128(row, ch), sh);
        cpa16(sbase + AT_KL(s) + swz128(row, ch), sl);
    }
    cpa_commit();
}

__global__ void __launch_bounds__(256, 2)
attn_tc(const void* __restrict__ maskp, const float* __restrict__ pos,
        bf16* __restrict__ Oh, bf16* __restrict__ Ol) {
    extern __shared__ char sm8[];
    const uint32_t sb = smem_u32(sm8);
    float* S = (float*)(sm8 + AT_S);
    unsigned char* mrow = (unsigned char*)(sm8 + AT_MR);

    const int blk = blockIdx.x;
    const int qt = blk & 7, h = (blk >> 3) & 7, b = blk >> 6;
    const int tid = threadIdx.x, wid = tid >> 5, lane = tid & 31;
    const int wm = wid >> 2, wn = wid & 3;          // 2 x 4 warp grid
    const int q0 = qt * 32;
    const int kind = g_mask_kind;

    const size_t hb = ((size_t)b * NH + h) * NN;
    const bf16* Qh = g_qhh + (hb + q0) * DH;
    const bf16* Ql = g_qhl + (hb + q0) * DH;
    const bf16* Kh = g_khh + hb * DH;
    const bf16* Kl = g_khl + hb * DH;
    const bf16* Vh = g_vhh + hb * DH;
    const bf16* Vl = g_vhl + hb * DH;

    // Prefetch K0 into stage 0
    issue_kv(sm8, 0, Kh, Kl, 0, tid);

    {
        int idx = b * NN + tid;
        bool mv;
        if (kind == 0)      mv = ((const int*)maskp)[idx] != 0;
        else if (kind == 1) mv = ((const float*)maskp)[idx] != 0.0f;
        else                mv = ((const unsigned char*)maskp)[idx] != 0;
        mrow[tid] = mv ? 1 : 0;
    }
    {
        int row = tid >> 3, ch = tid & 7;
        *(uint4*)(sm8 + AT_SQH + swz128(row, ch)) = *(const uint4*)(Qh + row * 64 + ch * 8);
        *(uint4*)(sm8 + AT_SQL + swz128(row, ch)) = *(const uint4*)(Ql + row * 64 + ch * 8);
    }
    const float* prow = pos + (size_t)b * (NH * NN * NN) + (size_t)q0 * NN;

    // ---- S = scale * Q K^T + pos, masked (HMMA) ----
    for (int kb = 0; kb < 4; kb++) {
        if (kb) __syncthreads();
        if (kb + 1 < 4) issue_kv(sm8, (kb + 1) & 1, Kh, Kl, kb + 1, tid);
        else            issue_kv(sm8, 0, Vh, Vl, 0, tid);   // V0 prefetch
        asm volatile("cp.async.wait_group %0;" :: "n"(1) : "memory");
        __syncthreads();

        const int st = kb & 1;
        float acc[2][4] = {{0.f,0.f,0.f,0.f},{0.f,0.f,0.f,0.f}};
        #pragma unroll
        for (int ks = 0; ks < 4; ks++) {
            const int arow = wm * 16 + (lane & 7) + ((lane >> 3) & 1) * 8;
            const int akch = ks * 2 + ((lane >> 4) & 1);
            const int nrow = wn * 16 + (lane & 7) + ((lane >> 4) & 1) * 8;
            const int nkch = ks * 2 + ((lane >> 3) & 1);
            uint32_t aH[4], aL[4], bH[4], bL[4];
            ldmA(aH, sb + AT_SQH + swz128(arow, akch));
            ldmA(aL, sb + AT_SQL + swz128(arow, akch));
            ldmB(bH, sb + AT_KH(st) + swz128(nrow, nkch));
            ldmB(bL, sb + AT_KL(st) + swz128(nrow, nkch));
            #pragma unroll
            for (int nt = 0; nt < 2; nt++) {
                mma16816(acc[nt], aH, bH + nt * 2);
                mma16816(acc[nt], aH, bL + nt * 2);
                mma16816(acc[nt], aL, bH + nt * 2);
            }
        }
        #pragma unroll
        for (int nt = 0; nt < 2; nt++) {
            int col = kb * 64 + wn * 16 + nt * 8 + (lane & 3) * 2;
            #pragma unroll
            for (int half = 0; half < 2; half++) {
                int r = wm * 16 + (lane >> 2) + half * 8;
                float a0 = acc[nt][half * 2 + 0], a1 = acc[nt][half * 2 + 1];
                float v0 = mrow[col]     ? -1e9f : fmaf(a0, 0.125f, prow[r * NN + col]);
                float v1 = mrow[col + 1] ? -1e9f : fmaf(a1, 0.125f, prow[r * NN + col + 1]);
                S[r * 264 + col]     = v0;
                S[r * 264 + col + 1] = v1;
            }
        }
    }
    __syncthreads();

    // ---- softmax: 8 lanes per row ----
    {
        int row = tid >> 3, sub = tid & 7;
        float* Sr = S + row * 264;
        float mx = -3.4e38f;
        #pragma unroll
        for (int t = 0; t < 32; t++) mx = fmaxf(mx, Sr[sub + t * 8]);
        #pragma unroll
        for (int o = 4; o > 0; o >>= 1)
            mx = fmaxf(mx, __shfl_xor_sync(0xffffffffu, mx, o));
        float ssum = 0.f;
        #pragma unroll
        for (int t = 0; t < 32; t++) {
            float e = __expf(Sr[sub + t * 8] - mx);
            Sr[sub + t * 8] = e;
            ssum += e;
        }
        #pragma unroll
        for (int o = 4; o > 0; o >>= 1)
            ssum += __shfl_xor_sync(0xffffffffu, ssum, o);
        float inv = 1.0f / ssum;
        #pragma unroll
        for (int t = 0; t < 32; t++) Sr[sub + t * 8] *= inv;
    }
    __syncthreads();

    // ---- convert P (fp32 S) -> bf16 hi/lo, overlaid on S region ----
    {
        int row = tid >> 3, cb = (tid & 7) * 4;
        float tmp[32];
        #pragma unroll
        for (int c4 = 0; c4 < 4; c4++)
            #pragma unroll
            for (int e = 0; e < 8; e++)
                tmp[c4 * 8 + e] = S[row * 264 + (cb + c4) * 8 + e];
        __syncthreads();
        #pragma unroll
        for (int c4 = 0; c4 < 4; c4++) {
            uint32_t hi4[4], lo4[4];
            #pragma unroll
            for (int p = 0; p < 4; p++) {
                float x0 = tmp[c4 * 8 + p * 2], x1 = tmp[c4 * 8 + p * 2 + 1];
                bf16 h0, l0, h1, l1;
                split2(x0, h0, l0); split2(x1, h1, l1);
                __nv_bfloat162 hp(h0, h1), lp(l0, l1);
                hi4[p] = *(uint32_t*)&hp;
                lo4[p] = *(uint32_t*)&lp;
            }
            *(uint4*)(sm8 + AT_PHI + swzP(row, cb + c4)) = make_uint4(hi4[0], hi4[1], hi4[2], hi4[3]);
            *(uint4*)(sm8 + AT_PLO + swzP(row, cb + c4)) = make_uint4(lo4[0], lo4[1], lo4[2], lo4[3]);
        }
    }

    // ---- O = P V (HMMA, V via ldmatrix.trans, double-buffered stages) ----
    float oacc[2][4] = {{0.f,0.f,0.f,0.f},{0.f,0.f,0.f,0.f}};
    for (int kb = 0; kb < 4; kb++) {
        __syncthreads();
        if (kb + 1 < 4) {
            issue_kv(sm8, (kb + 1) & 1, Vh, Vl, kb + 1, tid);
            asm volatile("cp.async.wait_group %0;" :: "n"(1) : "memory");
        } else {
            asm volatile("cp.async.wait_group %0;" :: "n"(0) : "memory");
        }
        __syncthreads();
        const int st = kb & 1;
        #pragma unroll
        for (int ks = 0; ks < 4; ks++) {
            const int arow = wm * 16 + (lane & 7) + ((lane >> 3) & 1) * 8;
            const int akch = kb * 8 + ks * 2 + ((lane >> 4) & 1);
            const int vrow = ks * 16 + (lane & 7) + ((lane >> 3) & 1) * 8;
            const int vch  = wn * 2 + ((lane >> 4) & 1);
            uint32_t pH[4], pL[4], vH[4], vL[4];
            ldmA(pH, sb + AT_PHI + swzP(arow, akch));
            ldmA(pL, sb + AT_PLO + swzP(arow, akch));
            ldmVT(vH, sb + AT_KH(st) + swz128(vrow, vch));
            ldmVT(vL, sb + AT_KL(st) + swz128(vrow, vch));
            #pragma unroll
            for (int nt = 0; nt < 2; nt++) {
                mma16816(oacc[nt], pH, vH + nt * 2);
                mma16816(oacc[nt], pH, vL + nt * 2);
                mma16816(oacc[nt], pL, vH + nt * 2);
            }
        }
    }

    // ---- store O directly as bf16 hi/lo (A of output projection) ----
    #pragma unroll
    for (int nt = 0; nt < 2; nt++) {
        int dcol = h * 64 + wn * 16 + nt * 8 + (lane & 3) * 2;
        #pragma unroll
        for (int half = 0; half < 2; half++) {
            int drow = q0 + wm * 16 + (lane >> 2) + half * 8;
            float x0 = oacc[nt][half * 2], x1 = oacc[nt][half * 2 + 1];
            bf16 h0, l0, h1, l1;
            split2(x0, h0, l0); split2(x1, h1, l1);
            size_t base = ((size_t)b * NN + drow) * DM + dcol;
            *(__nv_bfloat162*)&Oh[base] = __nv_bfloat162(h0, h1);
            *(__nv_bfloat162*)&Ol[base] = __nv_bfloat162(l0, l1);
        }
    }
}

// ---------------------------------------------------------------------------
extern "C" void kernel_launch(void* const* d_in, const int* in_sizes, int n_in,
                              void* d_out, int out_size) {
    const float *v, *k, *q, *box, *Wq, *bq, *Wk, *bk, *Wv, *bv, *Wm, *bm, *Wbox, *bbox;
    const void* mask;

    if (in_sizes[0] == BB * NN * DM) {
        v    = (const float*)d_in[0];
        k    = (const float*)d_in[1];
        q    = (const float*)d_in[2];
        box  = (const float*)d_in[3];
        mask = d_in[4];
        int wb = 5;
        for (int i = 5; i < n_in; i++) {
            if (in_sizes[i] == DM * DM) { wb = i; break; }
        }
        Wq   = (const float*)d_in[wb + 0];
        bq   = (const float*)d_in[wb + 1];
        Wk   = (const float*)d_in[wb + 2];
        bk   = (const float*)d_in[wb + 3];
        Wv   = (const float*)d_in[wb + 4];
        bv   = (const float*)d_in[wb + 5];
        Wm   = (const float*)d_in[wb + 6];
        bm   = (const float*)d_in[wb + 7];
        Wbox = (const float*)d_in[wb + 8];
        bbox = (const float*)d_in[wb + 9];
    } else {
        Wbox = (const float*)d_in[0];
        Wk   = (const float*)d_in[1];
        Wm   = (const float*)d_in[2];
        Wq   = (const float*)d_in[3];
        Wv   = (const float*)d_in[4];
        bbox = (const float*)d_in[5];
        bk   = (const float*)d_in[6];
        bm   = (const float*)d_in[7];
        bq   = (const float*)d_in[8];
        bv   = (const float*)d_in[9];
        box  = (const float*)d_in[10];
        int idx = 11;
        if (idx < n_in && in_sizes[idx] == 1) idx++;
        k    = (const float*)d_in[idx + 0];
        mask = d_in[idx + 1];
        q    = (const float*)d_in[idx + 2];
        v    = (const float*)d_in[idx + 3];
    }

    const size_t ATTED_ELEMS = (size_t)BB * NN * DM;
    const size_t POS_ELEMS   = (size_t)BB * NH * NN * NN;
    float* out = (float*)d_out;

    float *posA;
    bf16 *ahA, *alA, *aqhA, *aqlA, *wh4A, *wl4A;
    bf16 *qhhA, *qhlA, *khhA, *khlA, *vhhA, *vhlA;
    cudaGetSymbolAddress((void**)&posA, g_pos);
    cudaGetSymbolAddress((void**)&ahA,  g_ah);
    cudaGetSymbolAddress((void**)&alA,  g_al);
    cudaGetSymbolAddress((void**)&aqhA, g_aqh);
    cudaGetSymbolAddress((void**)&aqlA, g_aql);
    cudaGetSymbolAddress((void**)&wh4A, g_wh4);
    cudaGetSymbolAddress((void**)&wl4A, g_wl4);
    cudaGetSymbolAddress((void**)&qhhA, g_qhh);
    cudaGetSymbolAddress((void**)&qhlA, g_qhl);
    cudaGetSymbolAddress((void**)&khhA, g_khh);
    cudaGetSymbolAddress((void**)&khlA, g_khl);
    cudaGetSymbolAddress((void**)&vhhA, g_vhh);
    cudaGetSymbolAddress((void**)&vhlA, g_vhl);

    float* atted;
    float* pos_out;
    if ((size_t)out_size >= ATTED_ELEMS + POS_ELEMS) {
        atted   = out;
        pos_out = out + ATTED_ELEMS;
    } else if ((size_t)out_size == POS_ELEMS) {
        pos_out = out;
        atted   = posA;            // scratch sink (unused result)
    } else {
        atted   = out;
        pos_out = posA;
    }

    detect_mask_kind<<<1, 256>>>((const unsigned int*)mask);

    cudaFuncSetAttribute(gemm_qkv_pos,
                         cudaFuncAttributeMaxDynamicSharedMemorySize, 65536);
    cudaFuncSetAttribute(gemm_out,
                         cudaFuncAttributeMaxDynamicSharedMemorySize, 65536);
    cudaFuncSetAttribute(attn_tc,
                         cudaFuncAttributeMaxDynamicSharedMemorySize, AT_TOT);

    // Merged splits: q/k/v (12288 blocks) + 4 weights (4096 blocks)
    split_all<<<16384, 256>>>(q, k, v, Wq, Wk, Wv, Wm,
                              aqhA, aqlA, wh4A, wl4A);

    // Fused: 768 GEMM tile blocks + 8192 pos blocks in one launch
    gemm_qkv_pos<<<768 + BB * NN, 256, 65536>>>(
        aqhA, aqlA, wh4A, wl4A, bq, bk, bv,
        qhhA, qhlA, khhA, khlA, vhhA, vhlA,
        box, Wbox, bbox, pos_out);

    // Attention: 32-q tiles, 256 threads (R13 best config)
    attn_tc<<<BB * NH * 8, 256, AT_TOT>>>(mask, pos_out, ahA, alA);

    // Output projection
    gemm_out<<<dim3(4, 64), 256, 65536>>>(ahA, alA, wh4A, wl4A, bm, atted);
}

// round 17
// speedup vs baseline: 1.1175x; 1.0759x over previous
#include <cuda_runtime.h>
#include <cuda_bf16.h>
#include <cstdint>
#include <cstddef>

// Problem constants
#define BB   32
#define NN   256
#define DM   512
#define NH   8
#define DH   64

typedef unsigned long long ull;
typedef __nv_bfloat16 bf16;

// Scratch (allocation-free rule: __device__ globals)
__device__ float g_pos[BB*NH*NN*NN];  // pos_scores fallback when d_out lacks room
__device__ bf16  g_ah[BB*NN*DM];      // attn output hi split (A of final gemm)
__device__ bf16  g_al[BB*NN*DM];      // attn output lo split
__device__ bf16  g_aqh[3*BB*NN*DM];   // q,k,v input hi splits (3 slabs)
__device__ bf16  g_aql[3*BB*NN*DM];   // q,k,v input lo splits
__device__ bf16  g_wh4[4*DM*DM];      // W^T hi splits: Wq,Wk,Wv,Wm slabs
__device__ bf16  g_wl4[4*DM*DM];
__device__ bf16  g_qhh[BB*NH*NN*DH], g_qhl[BB*NH*NN*DH];  // Q heads hi/lo
__device__ bf16  g_khh[BB*NH*NN*DH], g_khl[BB*NH*NN*DH];  // K heads hi/lo
__device__ bf16  g_vhh[BB*NH*NN*DH], g_vhl[BB*NH*NN*DH];  // V heads hi/lo
__device__ int   g_mask_kind;         // 0=int32, 1=float32, 2=byte

// ---- HMMA helpers (baseline PTX, not 'a'-gated) ----
__device__ __forceinline__ uint32_t smem_u32(const void* p) {
    uint32_t a;
    asm("{ .reg .u64 t; cvta.to.shared.u64 t, %1; cvt.u32.u64 %0, t; }"
        : "=r"(a) : "l"(p));
    return a;
}
__device__ __forceinline__ void mma16816(float* c, const uint32_t* a,
                                         const uint32_t* b) {
    asm volatile(
        "mma.sync.aligned.m16n8k16.row.col.f32.bf16.bf16.f32 "
        "{%0,%1,%2,%3}, {%4,%5,%6,%7}, {%8,%9}, {%0,%1,%2,%3};"
        : "+f"(c[0]), "+f"(c[1]), "+f"(c[2]), "+f"(c[3])
        : "r"(a[0]), "r"(a[1]), "r"(a[2]), "r"(a[3]), "r"(b[0]), "r"(b[1]));
}
__device__ __forceinline__ void ldmA(uint32_t* r, uint32_t addr) {
    asm volatile("ldmatrix.sync.aligned.m8n8.x4.shared.b16 {%0,%1,%2,%3}, [%4];"
        : "=r"(r[0]), "=r"(r[1]), "=r"(r[2]), "=r"(r[3]) : "r"(addr));
}
__device__ __forceinline__ void ldmB(uint32_t* r, uint32_t addr) {
    asm volatile("ldmatrix.sync.aligned.m8n8.x4.shared.b16 {%0,%1,%2,%3}, [%4];"
        : "=r"(r[0]), "=r"(r[1]), "=r"(r[2]), "=r"(r[3]) : "r"(addr));
}
// trans variant: [k][n]-stored data -> b-fragment (V tiles)
__device__ __forceinline__ void ldmVT(uint32_t* r, uint32_t addr) {
    asm volatile("ldmatrix.sync.aligned.m8n8.x4.trans.shared.b16 {%0,%1,%2,%3}, [%4];"
        : "=r"(r[0]), "=r"(r[1]), "=r"(r[2]), "=r"(r[3]) : "r"(addr));
}
// gemm smem: 64B rows, 4x16B chunks
__device__ __forceinline__ int swz(int row, int ch) {
    return row * 64 + ((ch ^ ((row >> 1) & 3)) << 4);
}
// attn smem: 128B rows (64 bf16), 8x16B chunks
__device__ __forceinline__ int swz128(int row, int ch) {
    return row * 128 + ((ch ^ (row & 7)) << 4);
}
// P smem: 512B rows (256 bf16), 32x16B chunks
__device__ __forceinline__ int swzP(int row, int ch) {
    return row * 512 + ((ch ^ (row & 7)) << 4);
}
// bf16x2 element address within P buffer (col even)
__device__ __forceinline__ uint32_t paddr(int row, int col) {
    int ch = col >> 3;
    return row * 512 + ((ch ^ (row & 7)) << 4) + (col & 7) * 2;
}
// ---- cp.async (Ampere-baseline) ----
__device__ __forceinline__ void cpa16(uint32_t dst, const void* src) {
    asm volatile("cp.async.cg.shared.global [%0], [%1], 16;"
                 :: "r"(dst), "l"(src) : "memory");
}
__device__ __forceinline__ void cpa_commit() {
    asm volatile("cp.async.commit_group;" ::: "memory");
}
__device__ __forceinline__ void split2(float x, bf16& h, bf16& l) {
    h = __float2bfloat16(x);
    l = __float2bfloat16(x - __bfloat162float(h));
}

// ---------------------------------------------------------------------------
// Mask dtype sniffing (bool may arrive as u8/i32/f32).
// ---------------------------------------------------------------------------
__global__ void detect_mask_kind(const unsigned int* __restrict__ m) {
    __shared__ int oki, okf;
    if (threadIdx.x == 0) { oki = 1; okf = 1; }
    __syncthreads();
    for (int idx = threadIdx.x; idx < 2048; idx += 256) {
        unsigned int w = m[idx];
        if (w > 1u) oki = 0;
        if (w != 0u && w != 0x3F800000u) okf = 0;
    }
    __syncthreads();
    if (threadIdx.x == 0) g_mask_kind = oki ? 0 : (okf ? 1 : 2);
}

// ---------------------------------------------------------------------------
// Merged split kernel: blocks [0,12288) split q/k/v (float4 each);
// blocks [12288, 16384) split+transpose the 4 weights.
// ---------------------------------------------------------------------------
__global__ void split_all(const float* __restrict__ q,
                          const float* __restrict__ k,
                          const float* __restrict__ v,
                          const float* __restrict__ W0,
                          const float* __restrict__ W1,
                          const float* __restrict__ W2,
                          const float* __restrict__ W3,
                          bf16* __restrict__ ahi, bf16* __restrict__ alo,
                          bf16* __restrict__ whi, bf16* __restrict__ wlo) {
    const int bid = blockIdx.x;
    if (bid < 12288) {
        int gi = bid * 256 + threadIdx.x;
        const int SLAB4 = BB * NN * DM / 4;
        int slab = gi / SLAB4;
        int r4 = gi - slab * SLAB4;
        const float* src = (slab == 0) ? q : (slab == 1) ? k : v;
        int i = r4 * 4;
        float4 x = *(const float4*)(src + i);
        bf16 h0, l0, h1, l1, h2, l2, h3, l3;
        split2(x.x, h0, l0); split2(x.y, h1, l1);
        split2(x.z, h2, l2); split2(x.w, h3, l3);
        size_t o = (size_t)slab * (BB * NN * DM) + i;
        *(__nv_bfloat162*)(ahi + o)     = __nv_bfloat162(h0, h1);
        *(__nv_bfloat162*)(ahi + o + 2) = __nv_bfloat162(h2, h3);
        *(__nv_bfloat162*)(alo + o)     = __nv_bfloat162(l0, l1);
        *(__nv_bfloat162*)(alo + o + 2) = __nv_bfloat162(l2, l3);
    } else {
        int gi = (bid - 12288) * 256 + threadIdx.x;
        int w = gi >> 18, r = gi & 0x3FFFF;
        int kk = r >> 9, n = r & 511;
        const float* W = (w == 0) ? W0 : (w == 1) ? W1 : (w == 2) ? W2 : W3;
        float x = W[r];
        bf16 h, l; split2(x, h, l);
        size_t o = (size_t)w * (DM * DM) + n * 512 + kk;
        whi[o] = h;  wlo[o] = l;
    }
}

// ---------------------------------------------------------------------------
// HMMA GEMM body: cp.async 2-stage pipeline. CTA 128x128, 8 warps, BK=32.
// mode 0: fp32 row-major C.  mode 1: bf16 hi/lo head-split [B,H,N,DH].
// ---------------------------------------------------------------------------
__device__ __forceinline__ void issue_tile(
    uint32_t bs, int kn, int m0, int n0, int lr, int lr1, int lch,
    int so0, int so1,
    const bf16* __restrict__ Ah, const bf16* __restrict__ Al,
    const bf16* __restrict__ Bh, const bf16* __restrict__ Bl) {
    size_t ga0 = (size_t)(m0 + lr)  * 512 + kn + lch * 8;
    size_t ga1 = (size_t)(m0 + lr1) * 512 + kn + lch * 8;
    size_t gb0 = (size_t)(n0 + lr)  * 512 + kn + lch * 8;
    size_t gb1 = (size_t)(n0 + lr1) * 512 + kn + lch * 8;
    cpa16(bs +         so0, Ah + ga0);  cpa16(bs +         so1, Ah + ga1);
    cpa16(bs +  8192 + so0, Al + ga0);  cpa16(bs +  8192 + so1, Al + ga1);
    cpa16(bs + 16384 + so0, Bh + gb0);  cpa16(bs + 16384 + so1, Bh + gb1);
    cpa16(bs + 24576 + so0, Bl + gb0);  cpa16(bs + 24576 + so1, Bl + gb1);
    cpa_commit();
}

__device__ __forceinline__ void gemm_body(
    char* dsm, const bf16* __restrict__ Ah, const bf16* __restrict__ Al,
    const bf16* __restrict__ BhT, const bf16* __restrict__ BlT,
    const float* __restrict__ bias, float* __restrict__ C,
    bf16* __restrict__ Chi, bf16* __restrict__ Clo, int mode,
    int m0, int n0) {
    const uint32_t sb = smem_u32(dsm);
    const int tid = threadIdx.x, wid = tid >> 5, lane = tid & 31;
    const int wm = wid >> 2, wn = wid & 3;
    const int lr = tid >> 2, lch = tid & 3, lr1 = lr + 64;
    const int so0 = swz(lr, lch), so1 = swz(lr1, lch);

    float acc[4][4][4];
    #pragma unroll
    for (int i = 0; i < 4; i++)
        #pragma unroll
        for (int j = 0; j < 4; j++)
            #pragma unroll
            for (int t = 0; t < 4; t++) acc[i][j][t] = 0.f;

    issue_tile(sb, 0, m0, n0, lr, lr1, lch, so0, so1, Ah, Al, BhT, BlT);

    for (int c = 0; c < 16; c++) {
        if (c + 1 < 16) {
            issue_tile(sb + ((c + 1) & 1) * 32768, (c + 1) * 32,
                       m0, n0, lr, lr1, lch, so0, so1, Ah, Al, BhT, BlT);
            asm volatile("cp.async.wait_group %0;" :: "n"(1) : "memory");
        } else {
            asm volatile("cp.async.wait_group %0;" :: "n"(0) : "memory");
        }
        __syncthreads();

        const uint32_t bs = sb + (c & 1) * 32768;
        const uint32_t sbAh = bs, sbAl = bs + 8192;
        const uint32_t sbWh = bs + 16384, sbWl = bs + 24576;

        #pragma unroll
        for (int ks = 0; ks < 2; ks++) {
            const int arow = wm * 64 + (lane & 7) + ((lane >> 3) & 1) * 8;
            const int akch = ks * 2 + ((lane >> 4) & 1);
            const int nrow = wn * 32 + (lane & 7) + ((lane >> 4) & 1) * 8;
            const int nkch = ks * 2 + ((lane >> 3) & 1);

            uint32_t whf[2][4], wlf[2][4], af[4][4];
            #pragma unroll
            for (int g = 0; g < 2; g++) {
                ldmB(whf[g], sbWh + swz(nrow + g * 16, nkch));
                ldmB(wlf[g], sbWl + swz(nrow + g * 16, nkch));
            }
            #pragma unroll
            for (int mt = 0; mt < 4; mt++)
                ldmA(af[mt], sbAh + swz(arow + mt * 16, akch));
            #pragma unroll
            for (int mt = 0; mt < 4; mt++)
                #pragma unroll
                for (int nt = 0; nt < 4; nt++) {
                    mma16816(acc[mt][nt], af[mt], &whf[nt >> 1][(nt & 1) * 2]);
                    mma16816(acc[mt][nt], af[mt], &wlf[nt >> 1][(nt & 1) * 2]);
                }
            #pragma unroll
            for (int mt = 0; mt < 4; mt++)
                ldmA(af[mt], sbAl + swz(arow + mt * 16, akch));
            #pragma unroll
            for (int mt = 0; mt < 4; mt++)
                #pragma unroll
                for (int nt = 0; nt < 4; nt++)
                    mma16816(acc[mt][nt], af[mt], &whf[nt >> 1][(nt & 1) * 2]);
        }
        __syncthreads();
    }

    // ---- epilogue ----
    #pragma unroll
    for (int mt = 0; mt < 4; mt++) {
        int row = m0 + wm * 64 + mt * 16 + (lane >> 2);
        #pragma unroll
        for (int nt = 0; nt < 4; nt++) {
            int col = n0 + wn * 32 + nt * 8 + (lane & 3) * 2;
            float b0 = __ldg(&bias[col]), b1 = __ldg(&bias[col + 1]);
            float2 v0 = make_float2(acc[mt][nt][0] + b0, acc[mt][nt][1] + b1);
            float2 v1 = make_float2(acc[mt][nt][2] + b0, acc[mt][nt][3] + b1);
            if (mode == 1) {
                int h = col >> 6, d = col & 63;
                #pragma unroll
                for (int half = 0; half < 2; half++) {
                    float2 v = half ? v1 : v0;
                    int rr = row + half * 8;
                    int b = rr >> 8, n = rr & 255;
                    size_t base = (((size_t)b * NH + h) * NN + n) * DH + d;
                    bf16 h0, l0, h1, l1;
                    split2(v.x, h0, l0); split2(v.y, h1, l1);
                    *(__nv_bfloat162*)&Chi[base] = __nv_bfloat162(h0, h1);
                    *(__nv_bfloat162*)&Clo[base] = __nv_bfloat162(l0, l1);
                }
            } else {
                *(float2*)(C + (size_t)row * DM + col) = v0;
                *(float2*)(C + (size_t)(row + 8) * DM + col) = v1;
            }
        }
    }
}

// ---------------------------------------------------------------------------
// Fused launch: blocks [0,768) = Q/K/V projection tiles (tensor-bound);
// blocks [768, 768+8192) = geometric positional bias (MUFU-bound).
// ---------------------------------------------------------------------------
__global__ void __launch_bounds__(256, 2)
gemm_qkv_pos(const bf16* __restrict__ Aqh, const bf16* __restrict__ Aql,
             const bf16* __restrict__ Wh4, const bf16* __restrict__ Wl4,
             const float* __restrict__ bq, const float* __restrict__ bk,
             const float* __restrict__ bv,
             bf16* __restrict__ Qhh, bf16* __restrict__ Qhl,
             bf16* __restrict__ Khh, bf16* __restrict__ Khl,
             bf16* __restrict__ Vhh, bf16* __restrict__ Vhl,
             const float* __restrict__ box, const float* __restrict__ Wbox,
             const float* __restrict__ bbox, float* __restrict__ pos_out) {
    extern __shared__ char dsm[];
    const int bid = blockIdx.x;
    if (bid < 768) {
        int z = bid >> 8, rem = bid & 255;
        const size_t aoff = (size_t)z * (BB * NN * DM);
        const size_t woff = (size_t)z * (DM * DM);
        const float* bias = (z == 0) ? bq : (z == 1) ? bk : bv;
        bf16* Chi = (z == 0) ? Qhh : (z == 1) ? Khh : Vhh;
        bf16* Clo = (z == 0) ? Qhl : (z == 1) ? Khl : Vhl;
        gemm_body(dsm, Aqh + aoff, Aql + aoff, Wh4 + woff, Wl4 + woff,
                  bias, nullptr, Chi, Clo, 1, (rem >> 2) * 128, (rem & 3) * 128);
        return;
    }
    // ---- pos block ----
    float* scx = (float*)dsm;
    float* scy = scx + NN;
    float* slw = scy + NN;
    float* slh = slw + NN;
    float* wb  = slh + NN;     // 65 floats
    const int pid = bid - 768;
    const int i = pid & 255, b = pid >> 8;
    const int j = threadIdx.x;

    {
        const float* bj = box + ((size_t)b * NN + j) * 4;
        float x0 = bj[0], y0 = bj[1], x1 = bj[2], y1 = bj[3];
        scx[j] = 0.5f * (x0 + x1);
        scy[j] = 0.5f * (y0 + y1);
        slw[j] = __logf(x1 - x0 + 1.0f);
        slh[j] = __logf(y1 - y0 + 1.0f);
    }
    if (j < 64) wb[j] = Wbox[j];
    if (j == 0) wb[64] = bbox[0];
    __syncthreads();

    const float* bi = box + ((size_t)b * NN + i) * 4;
    float xi0 = bi[0], yi0 = bi[1], xi1 = bi[2], yi1 = bi[3];
    float cxi = 0.5f * (xi0 + xi1), cyi = 0.5f * (yi0 + yi1);
    float wi = xi1 - xi0 + 1.0f, hi = yi1 - yi0 + 1.0f;
    float invw = 1.0f / wi, invh = 1.0f / hi;
    float lwi = __logf(wi), lhi = __logf(hi);

    float p0 = __logf(fmaxf(fabsf((cxi - scx[j]) * invw), 1e-3f));
    float p1 = __logf(fmaxf(fabsf((cyi - scy[j]) * invh), 1e-3f));
    float p2 = lwi - slw[j];
    float p3 = lhi - slh[j];

    const float dmv[8] = {1.0f, 0.42169651f, 0.17782794f, 0.074989423f,
                          0.031622777f, 0.013335214f, 0.0056234132f, 0.0023713737f};
    float pc[4] = {100.f * p0, 100.f * p1, 100.f * p2, 100.f * p3};

    float s = wb[64];
    #pragma unroll
    for (int c = 0; c < 4; c++) {
        #pragma unroll
        for (int f = 0; f < 8; f++) {
            float m = pc[c] * dmv[f];
            float sn, cs;
            __sincosf(m, &sn, &cs);
            s = fmaf(sn, wb[c * 8 + f], s);
            s = fmaf(cs, wb[32 + c * 8 + f], s);
        }
    }
    float ps = fmaxf(s, 0.f);

    size_t base = (size_t)b * NH * NN * NN + (size_t)i * NN + j;
    #pragma unroll
    for (int hh = 0; hh < NH; hh++)
        pos_out[base + (size_t)hh * NN * NN] = ps;
}

// Output projection (mode 0, Wm = slab 3).
__global__ void __launch_bounds__(256, 2)
gemm_out(const bf16* __restrict__ Ah, const bf16* __restrict__ Al,
         const bf16* __restrict__ Wh4, const bf16* __restrict__ Wl4,
         const float* __restrict__ bias, float* __restrict__ C) {
    extern __shared__ char dsm[];
    gemm_body(dsm, Ah, Al, Wh4 + (size_t)3 * DM * DM, Wl4 + (size_t)3 * DM * DM,
              bias, C, nullptr, nullptr, 0, blockIdx.y * 128, blockIdx.x * 128);
}

// ---------------------------------------------------------------------------
// HMMA attention per (b, h, 32-q tile), register softmax (no-max variant):
// per kb: S frags -> exp in registers -> unnormalized P (bf16 hi/lo) straight
// to swizzled smem; row sums reduced via shfl + tiny smem; O scaled by 1/sum.
// smem: Qh 0..4K | Ql 4..8K | KV stages 8..40K | Phi 40960 | Plo 57344 |
//       sums[32][4] @73728 | invs[32] @74240 | mrow @74368. Total 74624.
// ---------------------------------------------------------------------------
#define AT_SQH 0
#define AT_SQL 4096
#define AT_KH(s) (8192 + (s) * 16384)
#define AT_KL(s) (16384 + (s) * 16384)
#define AT_PHI 40960
#define AT_PLO 57344
#define AT_SUM 73728
#define AT_INV 74240
#define AT_MR  74368
#define AT_TOT 74624

__device__ __forceinline__ void issue_kv(char* sm8, int s,
                                         const bf16* __restrict__ Gh,
                                         const bf16* __restrict__ Gl,
                                         int kb, int tid) {
    const uint32_t sbase = smem_u32(sm8);
    #pragma unroll
    for (int t = 0; t < 2; t++) {
        int idx = t * 256 + tid;
        int row = idx >> 3, ch = idx & 7;
        const bf16* sh = Gh + (size_t)(kb * 64 + row) * 64 + ch * 8;
        const bf16* sl = Gl + (size_t)(kb * 64 + row) * 64 + ch * 8;
        cpa16(sbase + AT_KH(s) + swz128(row, ch), sh);
        cpa16(sbase + AT_KL(s) + swz128(row, ch), sl);
    }
    cpa_commit();
}

__global__ void __launch_bounds__(256, 2)
attn_tc(const void* __restrict__ maskp, const float* __restrict__ pos,
        bf16* __restrict__ Oh, bf16* __restrict__ Ol) {
    extern __shared__ char sm8[];
    const uint32_t sb = smem_u32(sm8);
    unsigned char* mrow = (unsigned char*)(sm8 + AT_MR);

    const int blk = blockIdx.x;
    const int qt = blk & 7, h = (blk >> 3) & 7, b = blk >> 6;
    const int tid = threadIdx.x, wid = tid >> 5, lane = tid & 31;
    const int wm = wid >> 2, wn = wid & 3;          // 2 x 4 warp grid
    const int q0 = qt * 32;
    const int kind = g_mask_kind;

    const size_t hb = ((size_t)b * NH + h) * NN;
    const bf16* Qh = g_qhh + (hb + q0) * DH;
    const bf16* Ql = g_qhl + (hb + q0) * DH;
    const bf16* Kh = g_khh + hb * DH;
    const bf16* Kl = g_khl + hb * DH;
    const bf16* Vh = g_vhh + hb * DH;
    const bf16* Vl = g_vhl + hb * DH;

    // Prefetch K0 into stage 0
    issue_kv(sm8, 0, Kh, Kl, 0, tid);

    {
        int idx = b * NN + tid;
        bool mv;
        if (kind == 0)      mv = ((const int*)maskp)[idx] != 0;
        else if (kind == 1) mv = ((const float*)maskp)[idx] != 0.0f;
        else                mv = ((const unsigned char*)maskp)[idx] != 0;
        mrow[tid] = mv ? 1 : 0;
    }
    {
        int row = tid >> 3, ch = tid & 7;
        *(uint4*)(sm8 + AT_SQH + swz128(row, ch)) = *(const uint4*)(Qh + row * 64 + ch * 8);
        *(uint4*)(sm8 + AT_SQL + swz128(row, ch)) = *(const uint4*)(Ql + row * 64 + ch * 8);
    }
    const float* prow = pos + (size_t)b * (NH * NN * NN) + (size_t)q0 * NN;

    float rowsum[2] = {0.f, 0.f};

    // ---- per kb: S = scale*QK^T + pos (frags) -> exp -> P smem + row sums ----
    for (int kb = 0; kb < 4; kb++) {
        if (kb) __syncthreads();
        if (kb + 1 < 4) issue_kv(sm8, (kb + 1) & 1, Kh, Kl, kb + 1, tid);
        else            issue_kv(sm8, 0, Vh, Vl, 0, tid);   // V0 prefetch
        asm volatile("cp.async.wait_group %0;" :: "n"(1) : "memory");
        __syncthreads();

        const int st = kb & 1;
        float acc[2][4] = {{0.f,0.f,0.f,0.f},{0.f,0.f,0.f,0.f}};
        #pragma unroll
        for (int ks = 0; ks < 4; ks++) {
            const int arow = wm * 16 + (lane & 7) + ((lane >> 3) & 1) * 8;
            const int akch = ks * 2 + ((lane >> 4) & 1);
            const int nrow = wn * 16 + (lane & 7) + ((lane >> 4) & 1) * 8;
            const int nkch = ks * 2 + ((lane >> 3) & 1);
            uint32_t aH[4], aL[4], bH[4], bL[4];
            ldmA(aH, sb + AT_SQH + swz128(arow, akch));
            ldmA(aL, sb + AT_SQL + swz128(arow, akch));
            ldmB(bH, sb + AT_KH(st) + swz128(nrow, nkch));
            ldmB(bL, sb + AT_KL(st) + swz128(nrow, nkch));
            #pragma unroll
            for (int nt = 0; nt < 2; nt++) {
                mma16816(acc[nt], aH, bH + nt * 2);
                mma16816(acc[nt], aH, bL + nt * 2);
                mma16816(acc[nt], aL, bH + nt * 2);
            }
        }
        // register softmax numerator: e = exp(scale*s + pos), masked -> 0
        #pragma unroll
        for (int nt = 0; nt < 2; nt++) {
            int col = kb * 64 + wn * 16 + nt * 8 + (lane & 3) * 2;
            #pragma unroll
            for (int half = 0; half < 2; half++) {
                int r = wm * 16 + (lane >> 2) + half * 8;
                float a0 = acc[nt][half * 2 + 0], a1 = acc[nt][half * 2 + 1];
                float e0 = mrow[col]     ? 0.f
                         : __expf(fmaf(a0, 0.125f, prow[r * NN + col]));
                float e1 = mrow[col + 1] ? 0.f
                         : __expf(fmaf(a1, 0.125f, prow[r * NN + col + 1]));
                rowsum[half] += e0 + e1;
                bf16 h0, l0, h1, l1;
                split2(e0, h0, l0); split2(e1, h1, l1);
                __nv_bfloat162 hp(h0, h1), lp(l0, l1);
                uint32_t off = paddr(r, col);
                *(uint32_t*)(sm8 + AT_PHI + off) = *(uint32_t*)&hp;
                *(uint32_t*)(sm8 + AT_PLO + off) = *(uint32_t*)&lp;
            }
        }
    }

    // ---- reduce row sums: 4 lanes/row via shfl, 4 warps/row via smem ----
    #pragma unroll
    for (int half = 0; half < 2; half++) {
        rowsum[half] += __shfl_xor_sync(0xffffffffu, rowsum[half], 1);
        rowsum[half] += __shfl_xor_sync(0xffffffffu, rowsum[half], 2);
        if ((lane & 3) == 0) {
            int r = wm * 16 + (lane >> 2) + half * 8;
            ((float*)(sm8 + AT_SUM))[r * 4 + wn] = rowsum[half];
        }
    }
    __syncthreads();
    if (tid < 32) {
        const float* sp = (const float*)(sm8 + AT_SUM) + tid * 4;
        ((float*)(sm8 + AT_INV))[tid] = 1.0f / (sp[0] + sp[1] + sp[2] + sp[3]);
    }

    // ---- O = P V (HMMA, V via ldmatrix.trans, double-buffered stages) ----
    float oacc[2][4] = {{0.f,0.f,0.f,0.f},{0.f,0.f,0.f,0.f}};
    for (int kb = 0; kb < 4; kb++) {
        __syncthreads();                 // P writes / invs / prior stage reads done
        if (kb + 1 < 4) {
            issue_kv(sm8, (kb + 1) & 1, Vh, Vl, kb + 1, tid);
            asm volatile("cp.async.wait_group %0;" :: "n"(1) : "memory");
        } else {
            asm volatile("cp.async.wait_group %0;" :: "n"(0) : "memory");
        }
        __syncthreads();
        const int st = kb & 1;
        #pragma unroll
        for (int ks = 0; ks < 4; ks++) {
            const int arow = wm * 16 + (lane & 7) + ((lane >> 3) & 1) * 8;
            const int akch = kb * 8 + ks * 2 + ((lane >> 4) & 1);
            const int vrow = ks * 16 + (lane & 7) + ((lane >> 3) & 1) * 8;
            const int vch  = wn * 2 + ((lane >> 4) & 1);
            uint32_t pH[4], pL[4], vH[4], vL[4];
            ldmA(pH, sb + AT_PHI + swzP(arow, akch));
            ldmA(pL, sb + AT_PLO + swzP(arow, akch));
            ldmVT(vH, sb + AT_KH(st) + swz128(vrow, vch));
            ldmVT(vL, sb + AT_KL(st) + swz128(vrow, vch));
            #pragma unroll
            for (int nt = 0; nt < 2; nt++) {
                mma16816(oacc[nt], pH, vH + nt * 2);
                mma16816(oacc[nt], pH, vL + nt * 2);
                mma16816(oacc[nt], pL, vH + nt * 2);
            }
        }
    }

    // ---- store O scaled by 1/rowsum, as bf16 hi/lo (A of output proj) ----
    #pragma unroll
    for (int nt = 0; nt < 2; nt++) {
        int dcol = h * 64 + wn * 16 + nt * 8 + (lane & 3) * 2;
        #pragma unroll
        for (int half = 0; half < 2; half++) {
            int rloc = wm * 16 + (lane >> 2) + half * 8;
            float inv = ((const float*)(sm8 + AT_INV))[rloc];
            int drow = q0 + rloc;
            float x0 = oacc[nt][half * 2] * inv;
            float x1 = oacc[nt][half * 2 + 1] * inv;
            bf16 h0, l0, h1, l1;
            split2(x0, h0, l0); split2(x1, h1, l1);
            size_t base = ((size_t)b * NN + drow) * DM + dcol;
            *(__nv_bfloat162*)&Oh[base] = __nv_bfloat162(h0, h1);
            *(__nv_bfloat162*)&Ol[base] = __nv_bfloat162(l0, l1);
        }
    }
}

// ---------------------------------------------------------------------------
extern "C" void kernel_launch(void* const* d_in, const int* in_sizes, int n_in,
                              void* d_out, int out_size) {
    const float *v, *k, *q, *box, *Wq, *bq, *Wk, *bk, *Wv, *bv, *Wm, *bm, *Wbox, *bbox;
    const void* mask;

    if (in_sizes[0] == BB * NN * DM) {
        v    = (const float*)d_in[0];
        k    = (const float*)d_in[1];
        q    = (const float*)d_in[2];
        box  = (const float*)d_in[3];
        mask = d_in[4];
        int wb = 5;
        for (int i = 5; i < n_in; i++) {
            if (in_sizes[i] == DM * DM) { wb = i; break; }
        }
        Wq   = (const float*)d_in[wb + 0];
        bq   = (const float*)d_in[wb + 1];
        Wk   = (const float*)d_in[wb + 2];
        bk   = (const float*)d_in[wb + 3];
        Wv   = (const float*)d_in[wb + 4];
        bv   = (const float*)d_in[wb + 5];
        Wm   = (const float*)d_in[wb + 6];
        bm   = (const float*)d_in[wb + 7];
        Wbox = (const float*)d_in[wb + 8];
        bbox = (const float*)d_in[wb + 9];
    } else {
        Wbox = (const float*)d_in[0];
        Wk   = (const float*)d_in[1];
        Wm   = (const float*)d_in[2];
        Wq   = (const float*)d_in[3];
        Wv   = (const float*)d_in[4];
        bbox = (const float*)d_in[5];
        bk   = (const float*)d_in[6];
        bm   = (const float*)d_in[7];
        bq   = (const float*)d_in[8];
        bv   = (const float*)d_in[9];
        box  = (const float*)d_in[10];
        int idx = 11;
        if (idx < n_in && in_sizes[idx] == 1) idx++;
        k    = (const float*)d_in[idx + 0];
        mask = d_in[idx + 1];
        q    = (const float*)d_in[idx + 2];
        v    = (const float*)d_in[idx + 3];
    }

    const size_t ATTED_ELEMS = (size_t)BB * NN * DM;
    const size_t POS_ELEMS   = (size_t)BB * NH * NN * NN;
    float* out = (float*)d_out;

    float *posA;
    bf16 *ahA, *alA, *aqhA, *aqlA, *wh4A, *wl4A;
    bf16 *qhhA, *qhlA, *khhA, *khlA, *vhhA, *vhlA;
    cudaGetSymbolAddress((void**)&posA, g_pos);
    cudaGetSymbolAddress((void**)&ahA,  g_ah);
    cudaGetSymbolAddress((void**)&alA,  g_al);
    cudaGetSymbolAddress((void**)&aqhA, g_aqh);
    cudaGetSymbolAddress((void**)&aqlA, g_aql);
    cudaGetSymbolAddress((void**)&wh4A, g_wh4);
    cudaGetSymbolAddress((void**)&wl4A, g_wl4);
    cudaGetSymbolAddress((void**)&qhhA, g_qhh);
    cudaGetSymbolAddress((void**)&qhlA, g_qhl);
    cudaGetSymbolAddress((void**)&khhA, g_khh);
    cudaGetSymbolAddress((void**)&khlA, g_khl);
    cudaGetSymbolAddress((void**)&vhhA, g_vhh);
    cudaGetSymbolAddress((void**)&vhlA, g_vhl);

    float* atted;
    float* pos_out;
    if ((size_t)out_size >= ATTED_ELEMS + POS_ELEMS) {
        atted   = out;
        pos_out = out + ATTED_ELEMS;
    } else if ((size_t)out_size == POS_ELEMS) {
        pos_out = out;
        atted   = posA;            // scratch sink (unused result)
    } else {
        atted   = out;
        pos_out = posA;
    }

    detect_mask_kind<<<1, 256>>>((const unsigned int*)mask);

    cudaFuncSetAttribute(gemm_qkv_pos,
                         cudaFuncAttributeMaxDynamicSharedMemorySize, 65536);
    cudaFuncSetAttribute(gemm_out,
                         cudaFuncAttributeMaxDynamicSharedMemorySize, 65536);
    cudaFuncSetAttribute(attn_tc,
                         cudaFuncAttributeMaxDynamicSharedMemorySize, AT_TOT);

    // Merged splits: q/k/v (12288 blocks) + 4 weights (4096 blocks)
    split_all<<<16384, 256>>>(q, k, v, Wq, Wk, Wv, Wm,
                              aqhA, aqlA, wh4A, wl4A);

    // Fused: 768 GEMM tile blocks + 8192 pos blocks in one launch
    gemm_qkv_pos<<<768 + BB * NN, 256, 65536>>>(
        aqhA, aqlA, wh4A, wl4A, bq, bk, bv,
        qhhA, qhlA, khhA, khlA, vhhA, vhlA,
        box, Wbox, bbox, pos_out);

    // Attention: 32-q tiles, 256 threads, register softmax
    attn_tc<<<BB * NH * 8, 256, AT_TOT>>>(mask, pos_out, ahA, alA);

    // Output projection
    gemm_out<<<dim3(4, 64), 256, 65536>>>(ahA, alA, wh4A, wl4A, bm, atted);
}